// round 10
// baseline (speedup 1.0000x reference)
#include <cuda_runtime.h>
#include <cuda_bf16.h>
#include <cstdint>

#define BB 4
#define NN 1024
#define FF 256
#define HH 8
#define NF (NN*FF)

// ---------------- scratch (no allocations allowed) ----------------
__device__ float g_buf  [BB*NN*FF];
__device__ float p0_buf [BB*NN*FF];
__device__ float p1_buf [BB*NN*FF];
__device__ float y_buf  [BB*NN*FF];
__device__ float ex_buf [4*BB*HH*NN];   // es, es2, ed, ed2  each [bh][n]
__device__ float den_buf[BB*HH*NN];
__device__ unsigned adjb_buf[NN*32];    // adj bitmask: row i, 32 words over j
__device__ __nv_bfloat16 gthi_buf[BB*HH*32*NN];   // G^T hi  [bh][d][j]
__device__ __nv_bfloat16 gtlo_buf[BB*HH*32*NN];   // G^T lo

// ---------------- f32x2 helpers (sm_100+) ----------------
__device__ __forceinline__ unsigned long long pack2(float a, float b) {
    unsigned long long r;
    asm("mov.b64 %0, {%1, %2};" : "=l"(r) : "f"(a), "f"(b));
    return r;
}
__device__ __forceinline__ void ffma2(unsigned long long& acc,
                                      unsigned long long a, unsigned long long b) {
    asm("fma.rn.f32x2 %0, %1, %2, %0;" : "+l"(acc) : "l"(a), "l"(b));
}
union F4U2 { float4 f; ulonglong2 u; };

// ---------------- mma helpers ----------------
__device__ __forceinline__ uint32_t smem_u32(const void* p) {
    uint32_t a;
    asm("{ .reg .u64 t; cvta.to.shared.u64 t, %1; cvt.u32.u64 %0, t; }" : "=r"(a) : "l"(p));
    return a;
}
__device__ __forceinline__ uint32_t cvt2(float hi, float lo) {
    uint32_t r;
    asm("cvt.rn.bf16x2.f32 %0, %1, %2;" : "=r"(r) : "f"(hi), "f"(lo));
    return r;
}
__device__ __forceinline__ void ldm_x4(uint32_t& r0, uint32_t& r1, uint32_t& r2,
                                       uint32_t& r3, uint32_t addr) {
    asm volatile("ldmatrix.sync.aligned.m8n8.x4.shared.b16 {%0,%1,%2,%3}, [%4];"
                 : "=r"(r0), "=r"(r1), "=r"(r2), "=r"(r3) : "r"(addr));
}
__device__ __forceinline__ void mma16816(float* c, uint32_t a0, uint32_t a1,
                                         uint32_t a2, uint32_t a3,
                                         uint32_t b0, uint32_t b1) {
    asm volatile(
        "mma.sync.aligned.m16n8k16.row.col.f32.bf16.bf16.f32 "
        "{%0,%1,%2,%3}, {%4,%5,%6,%7}, {%8,%9}, {%0,%1,%2,%3};"
        : "+f"(c[0]), "+f"(c[1]), "+f"(c[2]), "+f"(c[3])
        : "r"(a0), "r"(a1), "r"(a2), "r"(a3), "r"(b0), "r"(b1));
}

// ---------------- GEMM: C[m][o] = sum_k A[m][k]*W[o][k] ----------------
__global__ __launch_bounds__(256) void gemm_nt(const float* __restrict__ A,
                                               const float* __restrict__ W,
                                               float* __restrict__ C) {
    __shared__ float As[16][68];
    __shared__ float Bs[16][68];
    const int m0 = blockIdx.y * 64;
    const int o0 = blockIdx.x * 64;
    const int tx = threadIdx.x & 15;
    const int ty = threadIdx.x >> 4;
    unsigned long long acc2[4][2];
    #pragma unroll
    for (int a = 0; a < 4; a++) { acc2[a][0] = 0ull; acc2[a][1] = 0ull; }
    for (int k0 = 0; k0 < 256; k0 += 16) {
        const int c = threadIdx.x & 15;
        const int r = threadIdx.x >> 4;
        #pragma unroll
        for (int rr = 0; rr < 64; rr += 16) {
            As[c][r + rr] = A[(m0 + r + rr) * 256 + k0 + c];
            Bs[c][r + rr] = W[(o0 + r + rr) * 256 + k0 + c];
        }
        __syncthreads();
        #pragma unroll
        for (int kk = 0; kk < 16; kk++) {
            F4U2 a4, b4;
            a4.f = *(const float4*)&As[kk][ty * 4];
            b4.f = *(const float4*)&Bs[kk][tx * 4];
            const unsigned long long ap0 = pack2(a4.f.x, a4.f.x);
            const unsigned long long ap1 = pack2(a4.f.y, a4.f.y);
            const unsigned long long ap2 = pack2(a4.f.z, a4.f.z);
            const unsigned long long ap3 = pack2(a4.f.w, a4.f.w);
            ffma2(acc2[0][0], ap0, b4.u.x); ffma2(acc2[0][1], ap0, b4.u.y);
            ffma2(acc2[1][0], ap1, b4.u.x); ffma2(acc2[1][1], ap1, b4.u.y);
            ffma2(acc2[2][0], ap2, b4.u.x); ffma2(acc2[2][1], ap2, b4.u.y);
            ffma2(acc2[3][0], ap3, b4.u.x); ffma2(acc2[3][1], ap3, b4.u.y);
        }
        __syncthreads();
    }
    #pragma unroll
    for (int a = 0; a < 4; a++) {
        F4U2 o;
        o.u.x = acc2[a][0];
        o.u.y = acc2[a][1];
        *(float4*)&C[(m0 + ty * 4 + a) * 256 + o0 + tx * 4] = o.f;
    }
}

// ---------------- adj -> bitmask ----------------
__global__ __launch_bounds__(32) void adjp_k(const int* __restrict__ adj,
                                             unsigned* __restrict__ adjb) {
    const int i = blockIdx.x, lane = threadIdx.x;
    #pragma unroll 4
    for (int w = 0; w < 32; ++w) {
        int v = adj[i * 1024 + w * 32 + lane];
        unsigned m = __ballot_sync(0xFFFFFFFFu, v != 0);
        if (lane == w) adjb[i * 32 + w] = m;
    }
}

// ---------------- src/dst projections -> exp tables; zero den ----------------
__global__ __launch_bounds__(256) void srcdst_k(const float* __restrict__ g,
                                                const float* __restrict__ a,
                                                float* __restrict__ es,
                                                float* __restrict__ es2,
                                                float* __restrict__ ed,
                                                float* __restrict__ ed2,
                                                float* __restrict__ den) {
    const int gtid = blockIdx.x * 256 + threadIdx.y * 32 + threadIdx.x;
    if (gtid < BB * HH * NN) den[gtid] = 0.f;
    const int row  = blockIdx.x * 8 + threadIdx.y;   // b*NN+n
    const int b = row >> 10, n = row & 1023;
    const int lane = threadIdx.x;
    const float as = a[lane];
    const float ad = a[32 + lane];
    const float* gr = g + row * 256;
    #pragma unroll
    for (int h = 0; h < HH; h++) {
        float v = gr[h * 32 + lane];
        float s = v * as;
        float d = v * ad;
        #pragma unroll
        for (int off = 16; off; off >>= 1) {
            s += __shfl_down_sync(0xFFFFFFFFu, s, off);
            d += __shfl_down_sync(0xFFFFFFFFu, d, off);
        }
        if (lane == 0) {
            const int idx = (b * HH + h) * NN + n;
            es [idx] = __expf(s);
            es2[idx] = __expf(0.2f * s);
            ed [idx] = __expf(d);
            ed2[idx] = __expf(0.2f * d);
        }
    }
}

// ---------------- den[bh][j] += sum_{i chunk} adj * max(es*ed, es2*ed2) ----------------
// grid (16 i-chunks of 64, HH, BB), 512 threads, 2 j per thread
__global__ __launch_bounds__(512) void denom_k(const unsigned* __restrict__ adjb,
                                               const float* __restrict__ es,
                                               const float* __restrict__ es2,
                                               const float* __restrict__ ed,
                                               const float* __restrict__ ed2,
                                               float* __restrict__ den) {
    __shared__ float ess[64], ess2[64];
    const int b = blockIdx.z, h = blockIdx.y, bh = b * HH + h;
    const int ic = blockIdx.x * 64;
    const int tid = threadIdx.x;
    if (tid < 64) ess[tid] = es[bh * NN + ic + tid];
    else if (tid < 128) ess2[tid - 64] = es2[bh * NN + ic + tid - 64];
    __syncthreads();
    const int j0 = tid, j1 = tid + 512;
    const float edj0 = ed[bh * NN + j0], ed2j0 = ed2[bh * NN + j0];
    const float edj1 = ed[bh * NN + j1], ed2j1 = ed2[bh * NN + j1];
    const int w0i = j0 >> 5, w1i = j1 >> 5, s0 = j0 & 31, s1 = j1 & 31;
    float a0 = 0.f, a1 = 0.f;
    #pragma unroll 8
    for (int i = 0; i < 64; ++i) {
        const unsigned* row = adjb + (size_t)(ic + i) * 32;
        const unsigned word0 = row[w0i];
        const unsigned word1 = row[w1i];
        const float esi = ess[i], es2i = ess2[i];
        const float v0 = fmaxf(esi * edj0, es2i * ed2j0);
        const float v1 = fmaxf(esi * edj1, es2i * ed2j1);
        if ((word0 >> s0) & 1u) a0 += v0;
        if ((word1 >> s1) & 1u) a1 += v1;
    }
    atomicAdd(&den[bh * NN + j0], a0);
    atomicAdd(&den[bh * NN + j1], a1);
}

// ---------------- gt: g transposed to [bh][d][j], split bf16 hi/lo (no den!) ----------------
__global__ __launch_bounds__(256) void gt_k(const float* __restrict__ g,
                                            __nv_bfloat16* __restrict__ gthi,
                                            __nv_bfloat16* __restrict__ gtlo) {
    __shared__ uint32_t sm[128][33];
    const int b = blockIdx.z, h = blockIdx.y, jc = blockIdx.x * 128;
    const int tid = threadIdx.x;
    const int jr0 = tid >> 3, c4 = (tid & 7) * 4;
    #pragma unroll
    for (int p = 0; p < 4; ++p) {
        const int jr = jr0 + p * 32;
        const int j = jc + jr;
        float4 v = *(const float4*)&g[(size_t)(b * NN + j) * FF + h * 32 + c4];
        float vs[4] = {v.x, v.y, v.z, v.w};
        #pragma unroll
        for (int q = 0; q < 4; ++q) {
            __nv_bfloat16 hi = __float2bfloat16(vs[q]);
            __nv_bfloat16 lo = __float2bfloat16(vs[q] - __bfloat162float(hi));
            sm[jr][c4 + q] = (uint32_t)__bfloat16_as_ushort(hi)
                           | ((uint32_t)__bfloat16_as_ushort(lo) << 16);
        }
    }
    __syncthreads();
    const int d = tid >> 3, j0 = (tid & 7) * 16;
    __align__(16) unsigned short his[16];
    __align__(16) unsigned short los[16];
    #pragma unroll
    for (int k = 0; k < 16; ++k) {
        uint32_t v = sm[j0 + k][d];
        his[k] = (unsigned short)(v & 0xFFFF);
        los[k] = (unsigned short)(v >> 16);
    }
    const size_t base = (size_t)((b * HH + h) * 32 + d) * NN + jc + j0;
    *(uint4*)&gthi[base]     = ((uint4*)his)[0];
    *(uint4*)&gthi[base + 8] = ((uint4*)his)[1];
    *(uint4*)&gtlo[base]     = ((uint4*)los)[0];
    *(uint4*)&gtlo[base + 8] = ((uint4*)los)[1];
}

// ---------------- attention via mma.sync bf16 (hi/lo 3-term), j-split x2 ----------------
// rden folded into staged eds: W' = adj*max(es*(ed*r), es2*(ed2*r)), G unnormalized.
// block = 8 warps x 16 i = 128 i rows, one (b, h, j-half). grid (8, 16, 4).
#define GROW 272   // 128 bf16 = 256B + 16B pad (conflict-free ldmatrix)

__device__ __forceinline__ float wv(float esr, float es2r, float2 e,
                                    unsigned bits, int c) {
    const float v = fmaxf(esr * e.x, es2r * e.y);
    return ((bits >> c) & 1u) ? v : 0.0f;
}

__global__ __launch_bounds__(256) void attn_k(const unsigned* __restrict__ adjb,
                                              const float* __restrict__ es,
                                              const float* __restrict__ es2,
                                              const float* __restrict__ ed,
                                              const float* __restrict__ ed2,
                                              const float* __restrict__ den,
                                              const __nv_bfloat16* __restrict__ gthi,
                                              const __nv_bfloat16* __restrict__ gtlo,
                                              float* __restrict__ part0,
                                              float* __restrict__ part1) {
    __shared__ __align__(16) char GsHi[32 * GROW];
    __shared__ __align__(16) char GsLo[32 * GROW];
    __shared__ float2 eds[NN / 2];
    __shared__ unsigned adjw[128][17];
    const int b = blockIdx.z;
    const int h = blockIdx.y & 7, jh = blockIdx.y >> 3;
    const int bh = b * HH + h;
    const int jbase = jh * (NN / 2);
    const int i0 = blockIdx.x * 128;
    const int tid = threadIdx.x, wid = tid >> 5, lane = tid & 31;
    const int g = lane >> 2, t = lane & 3;

    // stage ed/ed2 (this j-half) with 1/den folded in; adj words for this block
    for (int j = tid; j < NN / 2; j += 256) {
        const float r = 1.0f / den[bh * NN + jbase + j];
        eds[j] = make_float2(ed[bh * NN + jbase + j] * r,
                             ed2[bh * NN + jbase + j] * r);
    }
    for (int k = tid; k < 128 * 16; k += 256)
        adjw[k >> 4][k & 15] = adjb[(size_t)(i0 + (k >> 4)) * 32 + jh * 16 + (k & 15)];

    const int r0 = i0 + wid * 16 + g;                 // warp's row pair: r0, r0+8
    const float es_0  = es [bh * NN + r0];
    const float es_1  = es [bh * NN + r0 + 8];
    const float es2_0 = es2[bh * NN + r0];
    const float es2_1 = es2[bh * NN + r0 + 8];

    float acc[4][4] = {};
    const uint32_t gsHiA = smem_u32(GsHi), gsLoA = smem_u32(GsLo);
    const int d_l  = ((lane >> 4) & 1) * 8 + (lane & 7);
    const int jo_l = ((lane >> 3) & 1) * 8;
    const uint32_t lmoff = (uint32_t)(d_l * GROW + jo_l * 2);

    const __nv_bfloat16* ghb = gthi + (size_t)bh * 32 * NN + jbase;
    const __nv_bfloat16* glb = gtlo + (size_t)bh * 32 * NN + jbase;

    for (int ck = 0; ck < NN / 2; ck += 128) {
        __syncthreads();
        #pragma unroll
        for (int q = 0; q < 2; ++q) {
            const int idx = tid + q * 256;            // 0..511
            const int d = idx >> 4, c16 = idx & 15;
            const uint4 vh = *(const uint4*)(ghb + (size_t)d * NN + ck + c16 * 8);
            const uint4 vl = *(const uint4*)(glb + (size_t)d * NN + ck + c16 * 8);
            *(uint4*)(GsHi + d * GROW + c16 * 16) = vh;
            *(uint4*)(GsLo + d * GROW + c16 * 16) = vl;
        }
        __syncthreads();
        #pragma unroll
        for (int kk = 0; kk < 128; kk += 16) {
            const int jc = ck + kk;                   // local j within half
            const unsigned bits0 = adjw[wid * 16 + g][jc >> 5] >> (jc & 31);
            const unsigned bits1 = adjw[wid * 16 + g + 8][jc >> 5] >> (jc & 31);
            const float2 e0 = eds[jc + 2 * t];
            const float2 e1 = eds[jc + 2 * t + 1];
            const float2 e2 = eds[jc + 2 * t + 8];
            const float2 e3 = eds[jc + 2 * t + 9];
            const float w00 = wv(es_0, es2_0, e0, bits0, 2 * t);
            const float w01 = wv(es_0, es2_0, e1, bits0, 2 * t + 1);
            const float w02 = wv(es_0, es2_0, e2, bits0, 2 * t + 8);
            const float w03 = wv(es_0, es2_0, e3, bits0, 2 * t + 9);
            const float w10 = wv(es_1, es2_1, e0, bits1, 2 * t);
            const float w11 = wv(es_1, es2_1, e1, bits1, 2 * t + 1);
            const float w12 = wv(es_1, es2_1, e2, bits1, 2 * t + 8);
            const float w13 = wv(es_1, es2_1, e3, bits1, 2 * t + 9);
            const uint32_t ahi0 = cvt2(w01, w00);
            const uint32_t ahi1 = cvt2(w11, w10);
            const uint32_t ahi2 = cvt2(w03, w02);
            const uint32_t ahi3 = cvt2(w13, w12);
            const uint32_t alo0 = cvt2(w01 - __uint_as_float(ahi0 & 0xFFFF0000u),
                                       w00 - __uint_as_float(ahi0 << 16));
            const uint32_t alo1 = cvt2(w11 - __uint_as_float(ahi1 & 0xFFFF0000u),
                                       w10 - __uint_as_float(ahi1 << 16));
            const uint32_t alo2 = cvt2(w03 - __uint_as_float(ahi2 & 0xFFFF0000u),
                                       w02 - __uint_as_float(ahi2 << 16));
            const uint32_t alo3 = cvt2(w13 - __uint_as_float(ahi3 & 0xFFFF0000u),
                                       w12 - __uint_as_float(ahi3 << 16));
            uint32_t bh01[4], bh23[4], bl01[4], bl23[4];
            ldm_x4(bh01[0], bh01[1], bh01[2], bh01[3], gsHiA + lmoff + kk * 2);
            ldm_x4(bh23[0], bh23[1], bh23[2], bh23[3], gsHiA + lmoff + kk * 2 + 16 * GROW);
            ldm_x4(bl01[0], bl01[1], bl01[2], bl01[3], gsLoA + lmoff + kk * 2);
            ldm_x4(bl23[0], bl23[1], bl23[2], bl23[3], gsLoA + lmoff + kk * 2 + 16 * GROW);
            mma16816(acc[0], ahi0, ahi1, ahi2, ahi3, bh01[0], bh01[1]);
            mma16816(acc[0], ahi0, ahi1, ahi2, ahi3, bl01[0], bl01[1]);
            mma16816(acc[0], alo0, alo1, alo2, alo3, bh01[0], bh01[1]);
            mma16816(acc[1], ahi0, ahi1, ahi2, ahi3, bh01[2], bh01[3]);
            mma16816(acc[1], ahi0, ahi1, ahi2, ahi3, bl01[2], bl01[3]);
            mma16816(acc[1], alo0, alo1, alo2, alo3, bh01[2], bh01[3]);
            mma16816(acc[2], ahi0, ahi1, ahi2, ahi3, bh23[0], bh23[1]);
            mma16816(acc[2], ahi0, ahi1, ahi2, ahi3, bl23[0], bl23[1]);
            mma16816(acc[2], alo0, alo1, alo2, alo3, bh23[0], bh23[1]);
            mma16816(acc[3], ahi0, ahi1, ahi2, ahi3, bh23[2], bh23[3]);
            mma16816(acc[3], ahi0, ahi1, ahi2, ahi3, bl23[2], bl23[3]);
            mma16816(acc[3], alo0, alo1, alo2, alo3, bh23[2], bh23[3]);
        }
    }
    float* po = (jh ? part1 : part0) + (size_t)(b * NN + r0) * FF + h * 32;
    #pragma unroll
    for (int nt = 0; nt < 4; ++nt) {
        *(float2*)(po + nt * 8 + 2 * t) = make_float2(acc[nt][0], acc[nt][1]);
        *(float2*)(po + (size_t)8 * FF + nt * 8 + 2 * t) = make_float2(acc[nt][2], acc[nt][3]);
    }
}

// ---------------- BatchNorm over batch (B=4) + ReLU (+residual); sums 2 partials ----------------
template <bool ADDRES>
__global__ __launch_bounds__(256) void bn_k(const float* __restrict__ y0,
                                            const float* __restrict__ y1,
                                            const float* __restrict__ gamma,
                                            const float* __restrict__ beta,
                                            const float* __restrict__ resid,
                                            float* __restrict__ out) {
    const int p = blockIdx.x * 256 + threadIdx.x;
    const float v0 = y0[p]          + y1[p];
    const float v1 = y0[NF + p]     + y1[NF + p];
    const float v2 = y0[2 * NF + p] + y1[2 * NF + p];
    const float v3 = y0[3 * NF + p] + y1[3 * NF + p];
    const float mu = 0.25f * (v0 + v1 + v2 + v3);
    const float d0 = v0 - mu, d1 = v1 - mu, d2 = v2 - mu, d3 = v3 - mu;
    const float var = 0.25f * (d0 * d0 + d1 * d1 + d2 * d2 + d3 * d3);
    const float rs = rsqrtf(var + 1e-5f);
    const float ga = gamma[p] * rs;
    const float be = beta[p];
    float o0 = fmaxf(fmaf(ga, d0, be), 0.f);
    float o1 = fmaxf(fmaf(ga, d1, be), 0.f);
    float o2 = fmaxf(fmaf(ga, d2, be), 0.f);
    float o3 = fmaxf(fmaf(ga, d3, be), 0.f);
    if (ADDRES) {
        o0 += resid[p];
        o1 += resid[NF + p];
        o2 += resid[2 * NF + p];
        o3 += resid[3 * NF + p];
    }
    out[p] = o0;
    out[NF + p] = o1;
    out[2 * NF + p] = o2;
    out[3 * NF + p] = o3;
}

// ---------------- launch (two-stream fork/join: gt & adjp off critical path) ----------------
extern "C" void kernel_launch(void* const* d_in, const int* in_sizes, int n_in,
                              void* d_out, int out_size) {
    const float* x  = (const float*)d_in[0];
    const int*  adj = (const int*)  d_in[1];
    const float* W1 = (const float*)d_in[2];
    const float* a1 = (const float*)d_in[3];
    const float* g1 = (const float*)d_in[4];
    const float* b1 = (const float*)d_in[5];
    const float* W2 = (const float*)d_in[6];
    const float* a2 = (const float*)d_in[7];
    const float* g2 = (const float*)d_in[8];
    const float* b2 = (const float*)d_in[9];
    float* out = (float*)d_out;

    static float *pg = nullptr, *pp0, *pp1, *py, *pex, *pden;
    static unsigned* padjb;
    static __nv_bfloat16 *pgthi, *pgtlo;
    static cudaStream_t s2;
    static cudaEvent_t evStart, evAdj, evG1, evGt1, evG2, evGt2;
    if (!pg) {
        cudaGetSymbolAddress((void**)&pg,    g_buf);
        cudaGetSymbolAddress((void**)&pp0,   p0_buf);
        cudaGetSymbolAddress((void**)&pp1,   p1_buf);
        cudaGetSymbolAddress((void**)&py,    y_buf);
        cudaGetSymbolAddress((void**)&pex,   ex_buf);
        cudaGetSymbolAddress((void**)&pden,  den_buf);
        cudaGetSymbolAddress((void**)&padjb, adjb_buf);
        cudaGetSymbolAddress((void**)&pgthi, gthi_buf);
        cudaGetSymbolAddress((void**)&pgtlo, gtlo_buf);
        cudaStreamCreateWithFlags(&s2, cudaStreamNonBlocking);
        cudaEventCreateWithFlags(&evStart, cudaEventDisableTiming);
        cudaEventCreateWithFlags(&evAdj,   cudaEventDisableTiming);
        cudaEventCreateWithFlags(&evG1,    cudaEventDisableTiming);
        cudaEventCreateWithFlags(&evGt1,   cudaEventDisableTiming);
        cudaEventCreateWithFlags(&evG2,    cudaEventDisableTiming);
        cudaEventCreateWithFlags(&evGt2,   cudaEventDisableTiming);
    }
    const int EXN = BB * HH * NN;
    float* pes  = pex;
    float* pes2 = pex + EXN;
    float* ped  = pex + 2 * EXN;
    float* ped2 = pex + 3 * EXN;

    // fork side stream from capture origin
    cudaEventRecord(evStart, 0);
    cudaStreamWaitEvent(s2, evStart, 0);

    // ---- layer 1 ----
    adjp_k<<<1024, 32, 0, s2>>>(adj, padjb);               // s2: overlaps gemm1
    cudaEventRecord(evAdj, s2);

    gemm_nt<<<dim3(4, 64), 256>>>(x, W1, pg);
    cudaEventRecord(evG1, 0);
    cudaStreamWaitEvent(s2, evG1, 0);
    gt_k<<<dim3(8, 8, 4), 256, 0, s2>>>(pg, pgthi, pgtlo); // s2: overlaps srcdst+denom
    cudaEventRecord(evGt1, s2);

    srcdst_k<<<512, dim3(32, 8)>>>(pg, a1, pes, pes2, ped, ped2, pden);
    cudaStreamWaitEvent(0, evAdj, 0);
    denom_k<<<dim3(16, 8, 4), 512>>>(padjb, pes, pes2, ped, ped2, pden);
    cudaStreamWaitEvent(0, evGt1, 0);
    attn_k<<<dim3(8, 16, 4), 256>>>(padjb, pes, pes2, ped, ped2, pden,
                                    pgthi, pgtlo, pp0, pp1);
    bn_k<false><<<1024, 256>>>(pp0, pp1, g1, b1, nullptr, py);

    // ---- layer 2 ----
    gemm_nt<<<dim3(4, 64), 256>>>(py, W2, pg);
    cudaEventRecord(evG2, 0);
    cudaStreamWaitEvent(s2, evG2, 0);
    gt_k<<<dim3(8, 8, 4), 256, 0, s2>>>(pg, pgthi, pgtlo);
    cudaEventRecord(evGt2, s2);

    srcdst_k<<<512, dim3(32, 8)>>>(pg, a2, pes, pes2, ped, ped2, pden);
    denom_k<<<dim3(16, 8, 4), 512>>>(padjb, pes, pes2, ped, ped2, pden);
    cudaStreamWaitEvent(0, evGt2, 0);
    attn_k<<<dim3(8, 16, 4), 256>>>(padjb, pes, pes2, ped, ped2, pden,
                                    pgthi, pgtlo, pp0, pp1);
    bn_k<true><<<1024, 256>>>(pp0, pp1, g2, b2, x, out);
}

// round 11
// speedup vs baseline: 1.1316x; 1.1316x over previous
#include <cuda_runtime.h>
#include <cuda_bf16.h>
#include <cstdint>

#define BB 4
#define NN 1024
#define FF 256
#define HH 8
#define NF (NN*FF)

// ---------------- scratch (no allocations allowed) ----------------
__device__ float g_buf  [BB*NN*FF];
__device__ float p0_buf [BB*NN*FF];
__device__ float p1_buf [BB*NN*FF];
__device__ float y_buf  [BB*NN*FF];
__device__ float ex_buf [4*BB*HH*NN];   // es, es2, ed, ed2  each [bh][n]
__device__ float den_buf[BB*HH*NN];
__device__ unsigned adjb_buf [NN*32];   // row-major bits:  adjb[i][jw],  bit k = adj[i][jw*32+k]
__device__ unsigned adjbT_buf[NN*32];   // col-major bits:  adjbT[j][iw], bit k = adj[iw*32+k][j]
__device__ __nv_bfloat16 gthi_buf[BB*HH*32*NN];   // G^T hi  [bh][d][j]
__device__ __nv_bfloat16 gtlo_buf[BB*HH*32*NN];   // G^T lo

// ---------------- f32x2 helpers (sm_100+) ----------------
__device__ __forceinline__ unsigned long long pack2(float a, float b) {
    unsigned long long r;
    asm("mov.b64 %0, {%1, %2};" : "=l"(r) : "f"(a), "f"(b));
    return r;
}
__device__ __forceinline__ void ffma2(unsigned long long& acc,
                                      unsigned long long a, unsigned long long b) {
    asm("fma.rn.f32x2 %0, %1, %2, %0;" : "+l"(acc) : "l"(a), "l"(b));
}
union F4U2 { float4 f; ulonglong2 u; };

// ---------------- mma helpers ----------------
__device__ __forceinline__ uint32_t smem_u32(const void* p) {
    uint32_t a;
    asm("{ .reg .u64 t; cvta.to.shared.u64 t, %1; cvt.u32.u64 %0, t; }" : "=r"(a) : "l"(p));
    return a;
}
__device__ __forceinline__ uint32_t cvt2(float hi, float lo) {
    uint32_t r;
    asm("cvt.rn.bf16x2.f32 %0, %1, %2;" : "=r"(r) : "f"(hi), "f"(lo));
    return r;
}
__device__ __forceinline__ void ldm_x4(uint32_t& r0, uint32_t& r1, uint32_t& r2,
                                       uint32_t& r3, uint32_t addr) {
    asm volatile("ldmatrix.sync.aligned.m8n8.x4.shared.b16 {%0,%1,%2,%3}, [%4];"
                 : "=r"(r0), "=r"(r1), "=r"(r2), "=r"(r3) : "r"(addr));
}
__device__ __forceinline__ void mma16816(float* c, uint32_t a0, uint32_t a1,
                                         uint32_t a2, uint32_t a3,
                                         uint32_t b0, uint32_t b1) {
    asm volatile(
        "mma.sync.aligned.m16n8k16.row.col.f32.bf16.bf16.f32 "
        "{%0,%1,%2,%3}, {%4,%5,%6,%7}, {%8,%9}, {%0,%1,%2,%3};"
        : "+f"(c[0]), "+f"(c[1]), "+f"(c[2]), "+f"(c[3])
        : "r"(a0), "r"(a1), "r"(a2), "r"(a3), "r"(b0), "r"(b1));
}

// ---------------- GEMM: C[m][o] = sum_k A[m][k]*W[o][k] ----------------
__global__ __launch_bounds__(256) void gemm_nt(const float* __restrict__ A,
                                               const float* __restrict__ W,
                                               float* __restrict__ C) {
    __shared__ float As[16][68];
    __shared__ float Bs[16][68];
    const int m0 = blockIdx.y * 64;
    const int o0 = blockIdx.x * 64;
    const int tx = threadIdx.x & 15;
    const int ty = threadIdx.x >> 4;
    unsigned long long acc2[4][2];
    #pragma unroll
    for (int a = 0; a < 4; a++) { acc2[a][0] = 0ull; acc2[a][1] = 0ull; }
    for (int k0 = 0; k0 < 256; k0 += 16) {
        const int c = threadIdx.x & 15;
        const int r = threadIdx.x >> 4;
        #pragma unroll
        for (int rr = 0; rr < 64; rr += 16) {
            As[c][r + rr] = A[(m0 + r + rr) * 256 + k0 + c];
            Bs[c][r + rr] = W[(o0 + r + rr) * 256 + k0 + c];
        }
        __syncthreads();
        #pragma unroll
        for (int kk = 0; kk < 16; kk++) {
            F4U2 a4, b4;
            a4.f = *(const float4*)&As[kk][ty * 4];
            b4.f = *(const float4*)&Bs[kk][tx * 4];
            const unsigned long long ap0 = pack2(a4.f.x, a4.f.x);
            const unsigned long long ap1 = pack2(a4.f.y, a4.f.y);
            const unsigned long long ap2 = pack2(a4.f.z, a4.f.z);
            const unsigned long long ap3 = pack2(a4.f.w, a4.f.w);
            ffma2(acc2[0][0], ap0, b4.u.x); ffma2(acc2[0][1], ap0, b4.u.y);
            ffma2(acc2[1][0], ap1, b4.u.x); ffma2(acc2[1][1], ap1, b4.u.y);
            ffma2(acc2[2][0], ap2, b4.u.x); ffma2(acc2[2][1], ap2, b4.u.y);
            ffma2(acc2[3][0], ap3, b4.u.x); ffma2(acc2[3][1], ap3, b4.u.y);
        }
        __syncthreads();
    }
    #pragma unroll
    for (int a = 0; a < 4; a++) {
        F4U2 o;
        o.u.x = acc2[a][0];
        o.u.y = acc2[a][1];
        *(float4*)&C[(m0 + ty * 4 + a) * 256 + o0 + tx * 4] = o.f;
    }
}

// ---------------- adj -> row bitmask ----------------
__global__ __launch_bounds__(32) void adjp_k(const int* __restrict__ adj,
                                             unsigned* __restrict__ adjb) {
    const int i = blockIdx.x, lane = threadIdx.x;
    #pragma unroll 4
    for (int w = 0; w < 32; ++w) {
        int v = adj[i * 1024 + w * 32 + lane];
        unsigned m = __ballot_sync(0xFFFFFFFFu, v != 0);
        if (lane == w) adjb[i * 32 + w] = m;
    }
}

// ---------------- row bitmask -> column bitmask (32x32 bit-tile transpose) ----------------
__global__ __launch_bounds__(256) void adjt_k(const unsigned* __restrict__ adjb,
                                              unsigned* __restrict__ adjbT) {
    const int tile = blockIdx.x * 8 + threadIdx.y;   // 0..1023
    const int ti = tile >> 5;    // i-word block: rows ti*32..+31
    const int tj = tile & 31;    // j-word: cols tj*32..+31
    const int lane = threadIdx.x;
    const unsigned w = adjb[(ti * 32 + lane) * 32 + tj];
    #pragma unroll 4
    for (int jb = 0; jb < 32; ++jb) {
        unsigned m = __ballot_sync(0xFFFFFFFFu, (w >> jb) & 1u);
        if (lane == jb) adjbT[(tj * 32 + jb) * 32 + ti] = m;
    }
}

// ---------------- src/dst projections -> exp tables; zero den ----------------
__global__ __launch_bounds__(256) void srcdst_k(const float* __restrict__ g,
                                                const float* __restrict__ a,
                                                float* __restrict__ es,
                                                float* __restrict__ es2,
                                                float* __restrict__ ed,
                                                float* __restrict__ ed2,
                                                float* __restrict__ den) {
    const int gtid = blockIdx.x * 256 + threadIdx.y * 32 + threadIdx.x;
    if (gtid < BB * HH * NN) den[gtid] = 0.f;
    const int row  = blockIdx.x * 8 + threadIdx.y;   // b*NN+n
    const int b = row >> 10, n = row & 1023;
    const int lane = threadIdx.x;
    const float as = a[lane];
    const float ad = a[32 + lane];
    const float* gr = g + row * 256;
    #pragma unroll
    for (int h = 0; h < HH; h++) {
        float v = gr[h * 32 + lane];
        float s = v * as;
        float d = v * ad;
        #pragma unroll
        for (int off = 16; off; off >>= 1) {
            s += __shfl_down_sync(0xFFFFFFFFu, s, off);
            d += __shfl_down_sync(0xFFFFFFFFu, d, off);
        }
        if (lane == 0) {
            const int idx = (b * HH + h) * NN + n;
            es [idx] = __expf(s);
            es2[idx] = __expf(0.2f * s);
            ed [idx] = __expf(d);
            ed2[idx] = __expf(0.2f * d);
        }
    }
}

// ---------------- den[bh][j] += sum_{i chunk} adj * max(es*ed, es2*ed2) ----------------
// Transposed bitmask: 1 LDG per 32 i's per j. grid (16 i-chunks of 64, HH, BB), 512 thr, 2 j/thr.
__global__ __launch_bounds__(512) void denom_k(const unsigned* __restrict__ adjbT,
                                               const float* __restrict__ es,
                                               const float* __restrict__ es2,
                                               const float* __restrict__ ed,
                                               const float* __restrict__ ed2,
                                               float* __restrict__ den) {
    __shared__ float ess[64], ess2[64];
    const int b = blockIdx.z, h = blockIdx.y, bh = b * HH + h;
    const int ic = blockIdx.x * 64;
    const int tid = threadIdx.x;
    if (tid < 64) ess[tid] = es[bh * NN + ic + tid];
    else if (tid < 128) ess2[tid - 64] = es2[bh * NN + ic + tid - 64];
    __syncthreads();
    const int j0 = tid, j1 = tid + 512;
    const float edj0 = ed[bh * NN + j0], ed2j0 = ed2[bh * NN + j0];
    const float edj1 = ed[bh * NN + j1], ed2j1 = ed2[bh * NN + j1];
    const int wbase = ic >> 5;
    float a0 = 0.f, a1 = 0.f;
    #pragma unroll
    for (int w = 0; w < 2; ++w) {
        const unsigned word0 = adjbT[(size_t)j0 * 32 + wbase + w];
        const unsigned word1 = adjbT[(size_t)j1 * 32 + wbase + w];
        #pragma unroll 8
        for (int k = 0; k < 32; ++k) {
            const int i = w * 32 + k;
            const float esi = ess[i], es2i = ess2[i];
            const float v0 = fmaxf(esi * edj0, es2i * ed2j0);
            const float v1 = fmaxf(esi * edj1, es2i * ed2j1);
            if ((word0 >> k) & 1u) a0 += v0;
            if ((word1 >> k) & 1u) a1 += v1;
        }
    }
    atomicAdd(&den[bh * NN + j0], a0);
    atomicAdd(&den[bh * NN + j1], a1);
}

// ---------------- gt: g transposed to [bh][d][j], split bf16 hi/lo (den-free) ----------------
__global__ __launch_bounds__(256) void gt_k(const float* __restrict__ g,
                                            __nv_bfloat16* __restrict__ gthi,
                                            __nv_bfloat16* __restrict__ gtlo) {
    __shared__ uint32_t sm[128][33];
    const int b = blockIdx.z, h = blockIdx.y, jc = blockIdx.x * 128;
    const int tid = threadIdx.x;
    const int jr0 = tid >> 3, c4 = (tid & 7) * 4;
    #pragma unroll
    for (int p = 0; p < 4; ++p) {
        const int jr = jr0 + p * 32;
        const int j = jc + jr;
        float4 v = *(const float4*)&g[(size_t)(b * NN + j) * FF + h * 32 + c4];
        float vs[4] = {v.x, v.y, v.z, v.w};
        #pragma unroll
        for (int q = 0; q < 4; ++q) {
            __nv_bfloat16 hi = __float2bfloat16(vs[q]);
            __nv_bfloat16 lo = __float2bfloat16(vs[q] - __bfloat162float(hi));
            sm[jr][c4 + q] = (uint32_t)__bfloat16_as_ushort(hi)
                           | ((uint32_t)__bfloat16_as_ushort(lo) << 16);
        }
    }
    __syncthreads();
    const int d = tid >> 3, j0 = (tid & 7) * 16;
    __align__(16) unsigned short his[16];
    __align__(16) unsigned short los[16];
    #pragma unroll
    for (int k = 0; k < 16; ++k) {
        uint32_t v = sm[j0 + k][d];
        his[k] = (unsigned short)(v & 0xFFFF);
        los[k] = (unsigned short)(v >> 16);
    }
    const size_t base = (size_t)((b * HH + h) * 32 + d) * NN + jc + j0;
    *(uint4*)&gthi[base]     = ((uint4*)his)[0];
    *(uint4*)&gthi[base + 8] = ((uint4*)his)[1];
    *(uint4*)&gtlo[base]     = ((uint4*)los)[0];
    *(uint4*)&gtlo[base + 8] = ((uint4*)los)[1];
}

// ---------------- attention via mma.sync bf16 (hi/lo 3-term), j-split x2 ----------------
// rden folded into staged eds: W' = adj*max(es*(ed*r), es2*(ed2*r)), G unnormalized.
// block = 8 warps x 16 i = 128 i rows, one (b, h, j-half). grid (8, 16, 4).
#define GROW 272   // 128 bf16 = 256B + 16B pad (conflict-free ldmatrix)

__device__ __forceinline__ float wv(float esr, float es2r, float2 e,
                                    unsigned bits, int c) {
    const float v = fmaxf(esr * e.x, es2r * e.y);
    return ((bits >> c) & 1u) ? v : 0.0f;
}

__global__ __launch_bounds__(256) void attn_k(const unsigned* __restrict__ adjb,
                                              const float* __restrict__ es,
                                              const float* __restrict__ es2,
                                              const float* __restrict__ ed,
                                              const float* __restrict__ ed2,
                                              const float* __restrict__ den,
                                              const __nv_bfloat16* __restrict__ gthi,
                                              const __nv_bfloat16* __restrict__ gtlo,
                                              float* __restrict__ part0,
                                              float* __restrict__ part1) {
    __shared__ __align__(16) char GsHi[32 * GROW];
    __shared__ __align__(16) char GsLo[32 * GROW];
    __shared__ float2 eds[NN / 2];
    __shared__ unsigned adjw[128][17];
    const int b = blockIdx.z;
    const int h = blockIdx.y & 7, jh = blockIdx.y >> 3;
    const int bh = b * HH + h;
    const int jbase = jh * (NN / 2);
    const int i0 = blockIdx.x * 128;
    const int tid = threadIdx.x, wid = tid >> 5, lane = tid & 31;
    const int g = lane >> 2, t = lane & 3;

    // stage ed/ed2 (this j-half) with 1/den folded in; adj words for this block
    for (int j = tid; j < NN / 2; j += 256) {
        const float r = 1.0f / den[bh * NN + jbase + j];
        eds[j] = make_float2(ed[bh * NN + jbase + j] * r,
                             ed2[bh * NN + jbase + j] * r);
    }
    for (int k = tid; k < 128 * 16; k += 256)
        adjw[k >> 4][k & 15] = adjb[(size_t)(i0 + (k >> 4)) * 32 + jh * 16 + (k & 15)];

    const int r0 = i0 + wid * 16 + g;                 // warp's row pair: r0, r0+8
    const float es_0  = es [bh * NN + r0];
    const float es_1  = es [bh * NN + r0 + 8];
    const float es2_0 = es2[bh * NN + r0];
    const float es2_1 = es2[bh * NN + r0 + 8];

    float acc[4][4] = {};
    const uint32_t gsHiA = smem_u32(GsHi), gsLoA = smem_u32(GsLo);
    const int d_l  = ((lane >> 4) & 1) * 8 + (lane & 7);
    const int jo_l = ((lane >> 3) & 1) * 8;
    const uint32_t lmoff = (uint32_t)(d_l * GROW + jo_l * 2);

    const __nv_bfloat16* ghb = gthi + (size_t)bh * 32 * NN + jbase;
    const __nv_bfloat16* glb = gtlo + (size_t)bh * 32 * NN + jbase;

    for (int ck = 0; ck < NN / 2; ck += 128) {
        __syncthreads();
        #pragma unroll
        for (int q = 0; q < 2; ++q) {
            const int idx = tid + q * 256;            // 0..511
            const int d = idx >> 4, c16 = idx & 15;
            const uint4 vh = *(const uint4*)(ghb + (size_t)d * NN + ck + c16 * 8);
            const uint4 vl = *(const uint4*)(glb + (size_t)d * NN + ck + c16 * 8);
            *(uint4*)(GsHi + d * GROW + c16 * 16) = vh;
            *(uint4*)(GsLo + d * GROW + c16 * 16) = vl;
        }
        __syncthreads();
        #pragma unroll
        for (int kk = 0; kk < 128; kk += 16) {
            const int jc = ck + kk;                   // local j within half
            const unsigned bits0 = adjw[wid * 16 + g][jc >> 5] >> (jc & 31);
            const unsigned bits1 = adjw[wid * 16 + g + 8][jc >> 5] >> (jc & 31);
            const float2 e0 = eds[jc + 2 * t];
            const float2 e1 = eds[jc + 2 * t + 1];
            const float2 e2 = eds[jc + 2 * t + 8];
            const float2 e3 = eds[jc + 2 * t + 9];
            const float w00 = wv(es_0, es2_0, e0, bits0, 2 * t);
            const float w01 = wv(es_0, es2_0, e1, bits0, 2 * t + 1);
            const float w02 = wv(es_0, es2_0, e2, bits0, 2 * t + 8);
            const float w03 = wv(es_0, es2_0, e3, bits0, 2 * t + 9);
            const float w10 = wv(es_1, es2_1, e0, bits1, 2 * t);
            const float w11 = wv(es_1, es2_1, e1, bits1, 2 * t + 1);
            const float w12 = wv(es_1, es2_1, e2, bits1, 2 * t + 8);
            const float w13 = wv(es_1, es2_1, e3, bits1, 2 * t + 9);
            const uint32_t ahi0 = cvt2(w01, w00);
            const uint32_t ahi1 = cvt2(w11, w10);
            const uint32_t ahi2 = cvt2(w03, w02);
            const uint32_t ahi3 = cvt2(w13, w12);
            const uint32_t alo0 = cvt2(w01 - __uint_as_float(ahi0 & 0xFFFF0000u),
                                       w00 - __uint_as_float(ahi0 << 16));
            const uint32_t alo1 = cvt2(w11 - __uint_as_float(ahi1 & 0xFFFF0000u),
                                       w10 - __uint_as_float(ahi1 << 16));
            const uint32_t alo2 = cvt2(w03 - __uint_as_float(ahi2 & 0xFFFF0000u),
                                       w02 - __uint_as_float(ahi2 << 16));
            const uint32_t alo3 = cvt2(w13 - __uint_as_float(ahi3 & 0xFFFF0000u),
                                       w12 - __uint_as_float(ahi3 << 16));
            uint32_t bh01[4], bh23[4], bl01[4], bl23[4];
            ldm_x4(bh01[0], bh01[1], bh01[2], bh01[3], gsHiA + lmoff + kk * 2);
            ldm_x4(bh23[0], bh23[1], bh23[2], bh23[3], gsHiA + lmoff + kk * 2 + 16 * GROW);
            ldm_x4(bl01[0], bl01[1], bl01[2], bl01[3], gsLoA + lmoff + kk * 2);
            ldm_x4(bl23[0], bl23[1], bl23[2], bl23[3], gsLoA + lmoff + kk * 2 + 16 * GROW);
            mma16816(acc[0], ahi0, ahi1, ahi2, ahi3, bh01[0], bh01[1]);
            mma16816(acc[0], ahi0, ahi1, ahi2, ahi3, bl01[0], bl01[1]);
            mma16816(acc[0], alo0, alo1, alo2, alo3, bh01[0], bh01[1]);
            mma16816(acc[1], ahi0, ahi1, ahi2, ahi3, bh01[2], bh01[3]);
            mma16816(acc[1], ahi0, ahi1, ahi2, ahi3, bl01[2], bl01[3]);
            mma16816(acc[1], alo0, alo1, alo2, alo3, bh01[2], bh01[3]);
            mma16816(acc[2], ahi0, ahi1, ahi2, ahi3, bh23[0], bh23[1]);
            mma16816(acc[2], ahi0, ahi1, ahi2, ahi3, bl23[0], bl23[1]);
            mma16816(acc[2], alo0, alo1, alo2, alo3, bh23[0], bh23[1]);
            mma16816(acc[3], ahi0, ahi1, ahi2, ahi3, bh23[2], bh23[3]);
            mma16816(acc[3], ahi0, ahi1, ahi2, ahi3, bl23[2], bl23[3]);
            mma16816(acc[3], alo0, alo1, alo2, alo3, bh23[2], bh23[3]);
        }
    }
    float* po = (jh ? part1 : part0) + (size_t)(b * NN + r0) * FF + h * 32;
    #pragma unroll
    for (int nt = 0; nt < 4; ++nt) {
        *(float2*)(po + nt * 8 + 2 * t) = make_float2(acc[nt][0], acc[nt][1]);
        *(float2*)(po + (size_t)8 * FF + nt * 8 + 2 * t) = make_float2(acc[nt][2], acc[nt][3]);
    }
}

// ---------------- BatchNorm over batch (B=4) + ReLU (+residual); sums 2 partials ----------------
template <bool ADDRES>
__global__ __launch_bounds__(256) void bn_k(const float* __restrict__ y0,
                                            const float* __restrict__ y1,
                                            const float* __restrict__ gamma,
                                            const float* __restrict__ beta,
                                            const float* __restrict__ resid,
                                            float* __restrict__ out) {
    const int p = blockIdx.x * 256 + threadIdx.x;
    const float v0 = y0[p]          + y1[p];
    const float v1 = y0[NF + p]     + y1[NF + p];
    const float v2 = y0[2 * NF + p] + y1[2 * NF + p];
    const float v3 = y0[3 * NF + p] + y1[3 * NF + p];
    const float mu = 0.25f * (v0 + v1 + v2 + v3);
    const float d0 = v0 - mu, d1 = v1 - mu, d2 = v2 - mu, d3 = v3 - mu;
    const float var = 0.25f * (d0 * d0 + d1 * d1 + d2 * d2 + d3 * d3);
    const float rs = rsqrtf(var + 1e-5f);
    const float ga = gamma[p] * rs;
    const float be = beta[p];
    float o0 = fmaxf(fmaf(ga, d0, be), 0.f);
    float o1 = fmaxf(fmaf(ga, d1, be), 0.f);
    float o2 = fmaxf(fmaf(ga, d2, be), 0.f);
    float o3 = fmaxf(fmaf(ga, d3, be), 0.f);
    if (ADDRES) {
        o0 += resid[p];
        o1 += resid[NF + p];
        o2 += resid[2 * NF + p];
        o3 += resid[3 * NF + p];
    }
    out[p] = o0;
    out[NF + p] = o1;
    out[2 * NF + p] = o2;
    out[3 * NF + p] = o3;
}

// ---------------- launch (single stream) ----------------
extern "C" void kernel_launch(void* const* d_in, const int* in_sizes, int n_in,
                              void* d_out, int out_size) {
    const float* x  = (const float*)d_in[0];
    const int*  adj = (const int*)  d_in[1];
    const float* W1 = (const float*)d_in[2];
    const float* a1 = (const float*)d_in[3];
    const float* g1 = (const float*)d_in[4];
    const float* b1 = (const float*)d_in[5];
    const float* W2 = (const float*)d_in[6];
    const float* a2 = (const float*)d_in[7];
    const float* g2 = (const float*)d_in[8];
    const float* b2 = (const float*)d_in[9];
    float* out = (float*)d_out;

    static float *pg = nullptr, *pp0, *pp1, *py, *pex, *pden;
    static unsigned *padjb, *padjbT;
    static __nv_bfloat16 *pgthi, *pgtlo;
    if (!pg) {
        cudaGetSymbolAddress((void**)&pg,     g_buf);
        cudaGetSymbolAddress((void**)&pp0,    p0_buf);
        cudaGetSymbolAddress((void**)&pp1,    p1_buf);
        cudaGetSymbolAddress((void**)&py,     y_buf);
        cudaGetSymbolAddress((void**)&pex,    ex_buf);
        cudaGetSymbolAddress((void**)&pden,   den_buf);
        cudaGetSymbolAddress((void**)&padjb,  adjb_buf);
        cudaGetSymbolAddress((void**)&padjbT, adjbT_buf);
        cudaGetSymbolAddress((void**)&pgthi,  gthi_buf);
        cudaGetSymbolAddress((void**)&pgtlo,  gtlo_buf);
    }
    const int EXN = BB * HH * NN;
    float* pes  = pex;
    float* pes2 = pex + EXN;
    float* ped  = pex + 2 * EXN;
    float* ped2 = pex + 3 * EXN;

    adjp_k<<<1024, 32>>>(adj, padjb);
    adjt_k<<<128, dim3(32, 8)>>>(padjb, padjbT);

    // ---- layer 1 ----
    gemm_nt<<<dim3(4, 64), 256>>>(x, W1, pg);
    gt_k<<<dim3(8, 8, 4), 256>>>(pg, pgthi, pgtlo);
    srcdst_k<<<512, dim3(32, 8)>>>(pg, a1, pes, pes2, ped, ped2, pden);
    denom_k<<<dim3(16, 8, 4), 512>>>(padjbT, pes, pes2, ped, ped2, pden);
    attn_k<<<dim3(8, 16, 4), 256>>>(padjb, pes, pes2, ped, ped2, pden,
                                    pgthi, pgtlo, pp0, pp1);
    bn_k<false><<<1024, 256>>>(pp0, pp1, g1, b1, nullptr, py);

    // ---- layer 2 ----
    gemm_nt<<<dim3(4, 64), 256>>>(py, W2, pg);
    gt_k<<<dim3(8, 8, 4), 256>>>(pg, pgthi, pgtlo);
    srcdst_k<<<512, dim3(32, 8)>>>(pg, a2, pes, pes2, ped, ped2, pden);
    denom_k<<<dim3(16, 8, 4), 512>>>(padjbT, pes, pes2, ped, ped2, pden);
    attn_k<<<dim3(8, 16, 4), 256>>>(padjb, pes, pes2, ped, ped2, pden,
                                    pgthi, pgtlo, pp0, pp1);
    bn_k<true><<<1024, 256>>>(pp0, pp1, g2, b2, x, out);
}

// round 12
// speedup vs baseline: 1.2288x; 1.0860x over previous
#include <cuda_runtime.h>
#include <cuda_bf16.h>
#include <cstdint>

#define BB 4
#define NN 1024
#define FF 256
#define HH 8
#define NF (NN*FF)

// ---------------- scratch (no allocations allowed) ----------------
__device__ float p0_buf [BB*NN*FF];
__device__ float p1_buf [BB*NN*FF];
__device__ float y_buf  [BB*NN*FF];
__device__ float ex_buf [4*BB*HH*NN];   // es, es2, ed, ed2  each [bh][n]
__device__ float den_buf[BB*HH*NN];
__device__ unsigned adjb_buf [NN*32];   // row bits:  adjb[i][jw]
__device__ unsigned adjbT_buf[NN*32];   // col bits:  adjbT[j][iw]
__device__ __nv_bfloat16 gthi_buf[BB*HH*32*NN];   // G^T hi  [bh][d][j]
__device__ __nv_bfloat16 gtlo_buf[BB*HH*32*NN];   // G^T lo

// ---------------- f32x2 helpers ----------------
__device__ __forceinline__ unsigned long long pack2(float a, float b) {
    unsigned long long r;
    asm("mov.b64 %0, {%1, %2};" : "=l"(r) : "f"(a), "f"(b));
    return r;
}
__device__ __forceinline__ void ffma2(unsigned long long& acc,
                                      unsigned long long a, unsigned long long b) {
    asm("fma.rn.f32x2 %0, %1, %2, %0;" : "+l"(acc) : "l"(a), "l"(b));
}
union F4U2 { float4 f; ulonglong2 u; };

// ---------------- mma helpers ----------------
__device__ __forceinline__ uint32_t smem_u32(const void* p) {
    uint32_t a;
    asm("{ .reg .u64 t; cvta.to.shared.u64 t, %1; cvt.u32.u64 %0, t; }" : "=r"(a) : "l"(p));
    return a;
}
__device__ __forceinline__ uint32_t cvt2(float hi, float lo) {
    uint32_t r;
    asm("cvt.rn.bf16x2.f32 %0, %1, %2;" : "=r"(r) : "f"(hi), "f"(lo));
    return r;
}
__device__ __forceinline__ void ldm_x4(uint32_t& r0, uint32_t& r1, uint32_t& r2,
                                       uint32_t& r3, uint32_t addr) {
    asm volatile("ldmatrix.sync.aligned.m8n8.x4.shared.b16 {%0,%1,%2,%3}, [%4];"
                 : "=r"(r0), "=r"(r1), "=r"(r2), "=r"(r3) : "r"(addr));
}
__device__ __forceinline__ void mma16816(float* c, uint32_t a0, uint32_t a1,
                                         uint32_t a2, uint32_t a3,
                                         uint32_t b0, uint32_t b1) {
    asm volatile(
        "mma.sync.aligned.m16n8k16.row.col.f32.bf16.bf16.f32 "
        "{%0,%1,%2,%3}, {%4,%5,%6,%7}, {%8,%9}, {%0,%1,%2,%3};"
        : "+f"(c[0]), "+f"(c[1]), "+f"(c[2]), "+f"(c[3])
        : "r"(a0), "r"(a1), "r"(a2), "r"(a3), "r"(b0), "r"(b1));
}

// ---------------- fused GEMM + gt-transpose + src/dst exp tables + den zero ----------------
// C tile [64 m x 64 o]; o-tile = exactly 2 heads. Outputs:
//   gthi/gtlo [bh][d][j] bf16 hi/lo (via smem transpose)
//   es/es2/ed/ed2 [bh][n]           (via 8-lane shfl reduction)
//   den zeroed
__global__ __launch_bounds__(256) void gemm_fused(const float* __restrict__ A,
                                                  const float* __restrict__ W,
                                                  const float* __restrict__ av,
                                                  float* __restrict__ es,
                                                  float* __restrict__ es2,
                                                  float* __restrict__ ed,
                                                  float* __restrict__ ed2,
                                                  __nv_bfloat16* __restrict__ gthi,
                                                  __nv_bfloat16* __restrict__ gtlo,
                                                  float* __restrict__ den) {
    __shared__ float As[16][68];
    __shared__ float Bs[16][68];
    __shared__ uint32_t T[64][65];   // [o_local][m_local] packed hi|lo bf16
    const int m0 = blockIdx.y * 64;
    const int o0 = blockIdx.x * 64;
    const int tid = threadIdx.x;
    const int tx = tid & 15;
    const int ty = tid >> 4;

    // zero den (layer-local)
    const int gtid = (blockIdx.y * 4 + blockIdx.x) * 256 + tid;
    if (gtid < BB * HH * NN) den[gtid] = 0.f;

    unsigned long long acc2[4][2];
    #pragma unroll
    for (int a = 0; a < 4; a++) { acc2[a][0] = 0ull; acc2[a][1] = 0ull; }
    for (int k0 = 0; k0 < 256; k0 += 16) {
        const int c = tid & 15;
        const int r = tid >> 4;
        #pragma unroll
        for (int rr = 0; rr < 64; rr += 16) {
            As[c][r + rr] = A[(m0 + r + rr) * 256 + k0 + c];
            Bs[c][r + rr] = W[(o0 + r + rr) * 256 + k0 + c];
        }
        __syncthreads();
        #pragma unroll
        for (int kk = 0; kk < 16; kk++) {
            F4U2 a4, b4;
            a4.f = *(const float4*)&As[kk][ty * 4];
            b4.f = *(const float4*)&Bs[kk][tx * 4];
            const unsigned long long ap0 = pack2(a4.f.x, a4.f.x);
            const unsigned long long ap1 = pack2(a4.f.y, a4.f.y);
            const unsigned long long ap2 = pack2(a4.f.z, a4.f.z);
            const unsigned long long ap3 = pack2(a4.f.w, a4.f.w);
            ffma2(acc2[0][0], ap0, b4.u.x); ffma2(acc2[0][1], ap0, b4.u.y);
            ffma2(acc2[1][0], ap1, b4.u.x); ffma2(acc2[1][1], ap1, b4.u.y);
            ffma2(acc2[2][0], ap2, b4.u.x); ffma2(acc2[2][1], ap2, b4.u.y);
            ffma2(acc2[3][0], ap3, b4.u.x); ffma2(acc2[3][1], ap3, b4.u.y);
        }
        __syncthreads();
    }

    const int b  = m0 >> 10;          // batch (64 | 1024, so constant per block)
    const int j0 = m0 & 1023;         // j base within batch
    const int h0 = o0 >> 5;           // first head of this o-tile

    // per-column attention weights (d = col & 31; heads share a)
    float aws[4], awd[4];
    #pragma unroll
    for (int c = 0; c < 4; ++c) {
        const int d = (tx * 4 + c) & 31;
        aws[c] = av[d];
        awd[c] = av[32 + d];
    }

    float vv[4][4];
    #pragma unroll
    for (int a = 0; a < 4; a++) {
        F4U2 o;
        o.u.x = acc2[a][0];
        o.u.y = acc2[a][1];
        vv[a][0] = o.f.x; vv[a][1] = o.f.y; vv[a][2] = o.f.z; vv[a][3] = o.f.w;
        // pack hi/lo bf16 into transpose staging
        #pragma unroll
        for (int c = 0; c < 4; ++c) {
            const __nv_bfloat16 hi = __float2bfloat16(vv[a][c]);
            const __nv_bfloat16 lo = __float2bfloat16(vv[a][c] - __bfloat162float(hi));
            T[tx * 4 + c][ty * 4 + a] = (uint32_t)__bfloat16_as_ushort(hi)
                                      | ((uint32_t)__bfloat16_as_ushort(lo) << 16);
        }
    }

    // src/dst head-sums: reduce across 8 lanes (one head half of tx range)
    #pragma unroll
    for (int a = 0; a < 4; a++) {
        float s = vv[a][0] * aws[0] + vv[a][1] * aws[1]
                + vv[a][2] * aws[2] + vv[a][3] * aws[3];
        float d = vv[a][0] * awd[0] + vv[a][1] * awd[1]
                + vv[a][2] * awd[2] + vv[a][3] * awd[3];
        #pragma unroll
        for (int off = 4; off; off >>= 1) {
            s += __shfl_down_sync(0xFFFFFFFFu, s, off, 8);
            d += __shfl_down_sync(0xFFFFFFFFu, d, off, 8);
        }
        if ((tx & 7) == 0) {
            const int h = h0 + (tx >> 3);
            const int n = j0 + ty * 4 + a;
            const int idx = (b * HH + h) * NN + n;
            es [idx] = __expf(s);
            es2[idx] = __expf(0.2f * s);
            ed [idx] = __expf(d);
            ed2[idx] = __expf(0.2f * d);
        }
    }

    __syncthreads();
    // write transposed bf16 hi/lo: thread -> (d_local 0..63, 16-j quarter)
    {
        const int dl = tid >> 2;
        const int mq = (tid & 3) * 16;
        __align__(16) unsigned short his[16];
        __align__(16) unsigned short los[16];
        #pragma unroll
        for (int k = 0; k < 16; ++k) {
            const uint32_t v = T[dl][mq + k];
            his[k] = (unsigned short)(v & 0xFFFF);
            los[k] = (unsigned short)(v >> 16);
        }
        const int h = h0 + (dl >> 5);
        const int d = dl & 31;
        const size_t base = (size_t)((b * HH + h) * 32 + d) * NN + j0 + mq;
        *(uint4*)&gthi[base]     = ((uint4*)his)[0];
        *(uint4*)&gthi[base + 8] = ((uint4*)his)[1];
        *(uint4*)&gtlo[base]     = ((uint4*)los)[0];
        *(uint4*)&gtlo[base + 8] = ((uint4*)los)[1];
    }
}

// ---------------- adj -> row bitmask ----------------
__global__ __launch_bounds__(32) void adjp_k(const int* __restrict__ adj,
                                             unsigned* __restrict__ adjb) {
    const int i = blockIdx.x, lane = threadIdx.x;
    #pragma unroll 4
    for (int w = 0; w < 32; ++w) {
        int v = adj[i * 1024 + w * 32 + lane];
        unsigned m = __ballot_sync(0xFFFFFFFFu, v != 0);
        if (lane == w) adjb[i * 32 + w] = m;
    }
}

// ---------------- row bitmask -> column bitmask ----------------
__global__ __launch_bounds__(256) void adjt_k(const unsigned* __restrict__ adjb,
                                              unsigned* __restrict__ adjbT) {
    const int tile = blockIdx.x * 8 + threadIdx.y;
    const int ti = tile >> 5;
    const int tj = tile & 31;
    const int lane = threadIdx.x;
    const unsigned w = adjb[(ti * 32 + lane) * 32 + tj];
    #pragma unroll 4
    for (int jb = 0; jb < 32; ++jb) {
        unsigned m = __ballot_sync(0xFFFFFFFFu, (w >> jb) & 1u);
        if (lane == jb) adjbT[(tj * 32 + jb) * 32 + ti] = m;
    }
}

// ---------------- den[bh][j] += sum_{i chunk} adj * max(es*ed, es2*ed2) ----------------
__global__ __launch_bounds__(512) void denom_k(const unsigned* __restrict__ adjbT,
                                               const float* __restrict__ es,
                                               const float* __restrict__ es2,
                                               const float* __restrict__ ed,
                                               const float* __restrict__ ed2,
                                               float* __restrict__ den) {
    __shared__ float ess[64], ess2[64];
    const int b = blockIdx.z, h = blockIdx.y, bh = b * HH + h;
    const int ic = blockIdx.x * 64;
    const int tid = threadIdx.x;
    if (tid < 64) ess[tid] = es[bh * NN + ic + tid];
    else if (tid < 128) ess2[tid - 64] = es2[bh * NN + ic + tid - 64];
    __syncthreads();
    const int j0 = tid, j1 = tid + 512;
    const float edj0 = ed[bh * NN + j0], ed2j0 = ed2[bh * NN + j0];
    const float edj1 = ed[bh * NN + j1], ed2j1 = ed2[bh * NN + j1];
    const int wbase = ic >> 5;
    float a0 = 0.f, a1 = 0.f;
    #pragma unroll
    for (int w = 0; w < 2; ++w) {
        const unsigned word0 = adjbT[(size_t)j0 * 32 + wbase + w];
        const unsigned word1 = adjbT[(size_t)j1 * 32 + wbase + w];
        #pragma unroll 8
        for (int k = 0; k < 32; ++k) {
            const int i = w * 32 + k;
            const float esi = ess[i], es2i = ess2[i];
            const float v0 = fmaxf(esi * edj0, es2i * ed2j0);
            const float v1 = fmaxf(esi * edj1, es2i * ed2j1);
            if ((word0 >> k) & 1u) a0 += v0;
            if ((word1 >> k) & 1u) a1 += v1;
        }
    }
    atomicAdd(&den[bh * NN + j0], a0);
    atomicAdd(&den[bh * NN + j1], a1);
}

// ---------------- attention via mma.sync bf16 (hi/lo 3-term), j-split x2 ----------------
#define GROW 272

__device__ __forceinline__ float wv(float esr, float es2r, float2 e,
                                    unsigned bits, int c) {
    const float v = fmaxf(esr * e.x, es2r * e.y);
    return ((bits >> c) & 1u) ? v : 0.0f;
}

__global__ __launch_bounds__(256) void attn_k(const unsigned* __restrict__ adjb,
                                              const float* __restrict__ es,
                                              const float* __restrict__ es2,
                                              const float* __restrict__ ed,
                                              const float* __restrict__ ed2,
                                              const float* __restrict__ den,
                                              const __nv_bfloat16* __restrict__ gthi,
                                              const __nv_bfloat16* __restrict__ gtlo,
                                              float* __restrict__ part0,
                                              float* __restrict__ part1) {
    __shared__ __align__(16) char GsHi[32 * GROW];
    __shared__ __align__(16) char GsLo[32 * GROW];
    __shared__ float2 eds[NN / 2];
    __shared__ unsigned adjw[128][17];
    const int b = blockIdx.z;
    const int h = blockIdx.y & 7, jh = blockIdx.y >> 3;
    const int bh = b * HH + h;
    const int jbase = jh * (NN / 2);
    const int i0 = blockIdx.x * 128;
    const int tid = threadIdx.x, wid = tid >> 5, lane = tid & 31;
    const int g = lane >> 2, t = lane & 3;

    for (int j = tid; j < NN / 2; j += 256) {
        const float r = 1.0f / den[bh * NN + jbase + j];
        eds[j] = make_float2(ed[bh * NN + jbase + j] * r,
                             ed2[bh * NN + jbase + j] * r);
    }
    for (int k = tid; k < 128 * 16; k += 256)
        adjw[k >> 4][k & 15] = adjb[(size_t)(i0 + (k >> 4)) * 32 + jh * 16 + (k & 15)];

    const int r0 = i0 + wid * 16 + g;
    const float es_0  = es [bh * NN + r0];
    const float es_1  = es [bh * NN + r0 + 8];
    const float es2_0 = es2[bh * NN + r0];
    const float es2_1 = es2[bh * NN + r0 + 8];

    float acc[4][4] = {};
    const uint32_t gsHiA = smem_u32(GsHi), gsLoA = smem_u32(GsLo);
    const int d_l  = ((lane >> 4) & 1) * 8 + (lane & 7);
    const int jo_l = ((lane >> 3) & 1) * 8;
    const uint32_t lmoff = (uint32_t)(d_l * GROW + jo_l * 2);

    const __nv_bfloat16* ghb = gthi + (size_t)bh * 32 * NN + jbase;
    const __nv_bfloat16* glb = gtlo + (size_t)bh * 32 * NN + jbase;

    for (int ck = 0; ck < NN / 2; ck += 128) {
        __syncthreads();
        #pragma unroll
        for (int q = 0; q < 2; ++q) {
            const int idx = tid + q * 256;
            const int d = idx >> 4, c16 = idx & 15;
            const uint4 vh = *(const uint4*)(ghb + (size_t)d * NN + ck + c16 * 8);
            const uint4 vl = *(const uint4*)(glb + (size_t)d * NN + ck + c16 * 8);
            *(uint4*)(GsHi + d * GROW + c16 * 16) = vh;
            *(uint4*)(GsLo + d * GROW + c16 * 16) = vl;
        }
        __syncthreads();
        #pragma unroll
        for (int kk = 0; kk < 128; kk += 16) {
            const int jc = ck + kk;
            const unsigned bits0 = adjw[wid * 16 + g][jc >> 5] >> (jc & 31);
            const unsigned bits1 = adjw[wid * 16 + g + 8][jc >> 5] >> (jc & 31);
            const float2 e0 = eds[jc + 2 * t];
            const float2 e1 = eds[jc + 2 * t + 1];
            const float2 e2 = eds[jc + 2 * t + 8];
            const float2 e3 = eds[jc + 2 * t + 9];
            const float w00 = wv(es_0, es2_0, e0, bits0, 2 * t);
            const float w01 = wv(es_0, es2_0, e1, bits0, 2 * t + 1);
            const float w02 = wv(es_0, es2_0, e2, bits0, 2 * t + 8);
            const float w03 = wv(es_0, es2_0, e3, bits0, 2 * t + 9);
            const float w10 = wv(es_1, es2_1, e0, bits1, 2 * t);
            const float w11 = wv(es_1, es2_1, e1, bits1, 2 * t + 1);
            const float w12 = wv(es_1, es2_1, e2, bits1, 2 * t + 8);
            const float w13 = wv(es_1, es2_1, e3, bits1, 2 * t + 9);
            const uint32_t ahi0 = cvt2(w01, w00);
            const uint32_t ahi1 = cvt2(w11, w10);
            const uint32_t ahi2 = cvt2(w03, w02);
            const uint32_t ahi3 = cvt2(w13, w12);
            const uint32_t alo0 = cvt2(w01 - __uint_as_float(ahi0 & 0xFFFF0000u),
                                       w00 - __uint_as_float(ahi0 << 16));
            const uint32_t alo1 = cvt2(w11 - __uint_as_float(ahi1 & 0xFFFF0000u),
                                       w10 - __uint_as_float(ahi1 << 16));
            const uint32_t alo2 = cvt2(w03 - __uint_as_float(ahi2 & 0xFFFF0000u),
                                       w02 - __uint_as_float(ahi2 << 16));
            const uint32_t alo3 = cvt2(w13 - __uint_as_float(ahi3 & 0xFFFF0000u),
                                       w12 - __uint_as_float(ahi3 << 16));
            uint32_t bh01[4], bh23[4], bl01[4], bl23[4];
            ldm_x4(bh01[0], bh01[1], bh01[2], bh01[3], gsHiA + lmoff + kk * 2);
            ldm_x4(bh23[0], bh23[1], bh23[2], bh23[3], gsHiA + lmoff + kk * 2 + 16 * GROW);
            ldm_x4(bl01[0], bl01[1], bl01[2], bl01[3], gsLoA + lmoff + kk * 2);
            ldm_x4(bl23[0], bl23[1], bl23[2], bl23[3], gsLoA + lmoff + kk * 2 + 16 * GROW);
            mma16816(acc[0], ahi0, ahi1, ahi2, ahi3, bh01[0], bh01[1]);
            mma16816(acc[0], ahi0, ahi1, ahi2, ahi3, bl01[0], bl01[1]);
            mma16816(acc[0], alo0, alo1, alo2, alo3, bh01[0], bh01[1]);
            mma16816(acc[1], ahi0, ahi1, ahi2, ahi3, bh01[2], bh01[3]);
            mma16816(acc[1], ahi0, ahi1, ahi2, ahi3, bl01[2], bl01[3]);
            mma16816(acc[1], alo0, alo1, alo2, alo3, bh01[2], bh01[3]);
            mma16816(acc[2], ahi0, ahi1, ahi2, ahi3, bh23[0], bh23[1]);
            mma16816(acc[2], ahi0, ahi1, ahi2, ahi3, bl23[0], bl23[1]);
            mma16816(acc[2], alo0, alo1, alo2, alo3, bh23[0], bh23[1]);
            mma16816(acc[3], ahi0, ahi1, ahi2, ahi3, bh23[2], bh23[3]);
            mma16816(acc[3], ahi0, ahi1, ahi2, ahi3, bl23[2], bl23[3]);
            mma16816(acc[3], alo0, alo1, alo2, alo3, bh23[2], bh23[3]);
        }
    }
    float* po = (jh ? part1 : part0) + (size_t)(b * NN + r0) * FF + h * 32;
    #pragma unroll
    for (int nt = 0; nt < 4; ++nt) {
        *(float2*)(po + nt * 8 + 2 * t) = make_float2(acc[nt][0], acc[nt][1]);
        *(float2*)(po + (size_t)8 * FF + nt * 8 + 2 * t) = make_float2(acc[nt][2], acc[nt][3]);
    }
}

// ---------------- BatchNorm over batch (B=4) + ReLU (+residual); sums 2 partials ----------------
template <bool ADDRES>
__global__ __launch_bounds__(256) void bn_k(const float* __restrict__ y0,
                                            const float* __restrict__ y1,
                                            const float* __restrict__ gamma,
                                            const float* __restrict__ beta,
                                            const float* __restrict__ resid,
                                            float* __restrict__ out) {
    const int p = blockIdx.x * 256 + threadIdx.x;
    const float v0 = y0[p]          + y1[p];
    const float v1 = y0[NF + p]     + y1[NF + p];
    const float v2 = y0[2 * NF + p] + y1[2 * NF + p];
    const float v3 = y0[3 * NF + p] + y1[3 * NF + p];
    const float mu = 0.25f * (v0 + v1 + v2 + v3);
    const float d0 = v0 - mu, d1 = v1 - mu, d2 = v2 - mu, d3 = v3 - mu;
    const float var = 0.25f * (d0 * d0 + d1 * d1 + d2 * d2 + d3 * d3);
    const float rs = rsqrtf(var + 1e-5f);
    const float ga = gamma[p] * rs;
    const float be = beta[p];
    float o0 = fmaxf(fmaf(ga, d0, be), 0.f);
    float o1 = fmaxf(fmaf(ga, d1, be), 0.f);
    float o2 = fmaxf(fmaf(ga, d2, be), 0.f);
    float o3 = fmaxf(fmaf(ga, d3, be), 0.f);
    if (ADDRES) {
        o0 += resid[p];
        o1 += resid[NF + p];
        o2 += resid[2 * NF + p];
        o3 += resid[3 * NF + p];
    }
    out[p] = o0;
    out[NF + p] = o1;
    out[2 * NF + p] = o2;
    out[3 * NF + p] = o3;
}

// ---------------- launch (single stream, 10 kernels) ----------------
extern "C" void kernel_launch(void* const* d_in, const int* in_sizes, int n_in,
                              void* d_out, int out_size) {
    const float* x  = (const float*)d_in[0];
    const int*  adj = (const int*)  d_in[1];
    const float* W1 = (const float*)d_in[2];
    const float* a1 = (const float*)d_in[3];
    const float* g1 = (const float*)d_in[4];
    const float* b1 = (const float*)d_in[5];
    const float* W2 = (const float*)d_in[6];
    const float* a2 = (const float*)d_in[7];
    const float* g2 = (const float*)d_in[8];
    const float* b2 = (const float*)d_in[9];
    float* out = (float*)d_out;

    static float *pp0 = nullptr, *pp1, *py, *pex, *pden;
    static unsigned *padjb, *padjbT;
    static __nv_bfloat16 *pgthi, *pgtlo;
    if (!pp0) {
        cudaGetSymbolAddress((void**)&pp0,    p0_buf);
        cudaGetSymbolAddress((void**)&pp1,    p1_buf);
        cudaGetSymbolAddress((void**)&py,     y_buf);
        cudaGetSymbolAddress((void**)&pex,    ex_buf);
        cudaGetSymbolAddress((void**)&pden,   den_buf);
        cudaGetSymbolAddress((void**)&padjb,  adjb_buf);
        cudaGetSymbolAddress((void**)&padjbT, adjbT_buf);
        cudaGetSymbolAddress((void**)&pgthi,  gthi_buf);
        cudaGetSymbolAddress((void**)&pgtlo,  gtlo_buf);
    }
    const int EXN = BB * HH * NN;
    float* pes  = pex;
    float* pes2 = pex + EXN;
    float* ped  = pex + 2 * EXN;
    float* ped2 = pex + 3 * EXN;

    adjp_k<<<1024, 32>>>(adj, padjb);
    adjt_k<<<128, dim3(32, 8)>>>(padjb, padjbT);

    // ---- layer 1 ----
    gemm_fused<<<dim3(4, 64), 256>>>(x, W1, a1, pes, pes2, ped, ped2,
                                     pgthi, pgtlo, pden);
    denom_k<<<dim3(16, 8, 4), 512>>>(padjbT, pes, pes2, ped, ped2, pden);
    attn_k<<<dim3(8, 16, 4), 256>>>(padjb, pes, pes2, ped, ped2, pden,
                                    pgthi, pgtlo, pp0, pp1);
    bn_k<false><<<1024, 256>>>(pp0, pp1, g1, b1, nullptr, py);

    // ---- layer 2 ----
    gemm_fused<<<dim3(4, 64), 256>>>(py, W2, a2, pes, pes2, ped, ped2,
                                     pgthi, pgtlo, pden);
    denom_k<<<dim3(16, 8, 4), 512>>>(padjbT, pes, pes2, ped, ped2, pden);
    attn_k<<<dim3(8, 16, 4), 256>>>(padjb, pes, pes2, ped, ped2, pden,
                                    pgthi, pgtlo, pp0, pp1);
    bn_k<true><<<1024, 256>>>(pp0, pp1, g2, b2, x, out);
}

// round 13
// speedup vs baseline: 1.2464x; 1.0143x over previous
#include <cuda_runtime.h>
#include <cuda_bf16.h>
#include <cstdint>

#define BB 4
#define NN 1024
#define FF 256
#define HH 8
#define NF (NN*FF)

// ---------------- scratch (no allocations allowed) ----------------
__device__ float p0_buf [BB*NN*FF];
__device__ float p1_buf [BB*NN*FF];
__device__ float y_buf  [BB*NN*FF];
__device__ float ex_buf [4*BB*HH*NN];   // es, es2, ed, ed2  each [bh][n]
__device__ float den_buf[BB*HH*NN];
__device__ unsigned adjb_buf [NN*32];   // row bits:  adjb[i][jw]
__device__ unsigned adjbT_buf[NN*32];   // col bits:  adjbT[j][iw]
__device__ __nv_bfloat16 gthi_buf[BB*HH*32*NN];   // G^T hi  [bh][d][j]
__device__ __nv_bfloat16 gtlo_buf[BB*HH*32*NN];   // G^T lo

// ---------------- f32x2 helpers ----------------
__device__ __forceinline__ unsigned long long pack2(float a, float b) {
    unsigned long long r;
    asm("mov.b64 %0, {%1, %2};" : "=l"(r) : "f"(a), "f"(b));
    return r;
}
__device__ __forceinline__ void ffma2(unsigned long long& acc,
                                      unsigned long long a, unsigned long long b) {
    asm("fma.rn.f32x2 %0, %1, %2, %0;" : "+l"(acc) : "l"(a), "l"(b));
}
union F4U2 { float4 f; ulonglong2 u; };

// ---------------- mma helpers ----------------
__device__ __forceinline__ uint32_t smem_u32(const void* p) {
    uint32_t a;
    asm("{ .reg .u64 t; cvta.to.shared.u64 t, %1; cvt.u32.u64 %0, t; }" : "=r"(a) : "l"(p));
    return a;
}
__device__ __forceinline__ uint32_t cvt2(float hi, float lo) {
    uint32_t r;
    asm("cvt.rn.bf16x2.f32 %0, %1, %2;" : "=r"(r) : "f"(hi), "f"(lo));
    return r;
}
__device__ __forceinline__ void ldm_x4(uint32_t& r0, uint32_t& r1, uint32_t& r2,
                                       uint32_t& r3, uint32_t addr) {
    asm volatile("ldmatrix.sync.aligned.m8n8.x4.shared.b16 {%0,%1,%2,%3}, [%4];"
                 : "=r"(r0), "=r"(r1), "=r"(r2), "=r"(r3) : "r"(addr));
}
__device__ __forceinline__ void mma16816(float* c, uint32_t a0, uint32_t a1,
                                         uint32_t a2, uint32_t a3,
                                         uint32_t b0, uint32_t b1) {
    asm volatile(
        "mma.sync.aligned.m16n8k16.row.col.f32.bf16.bf16.f32 "
        "{%0,%1,%2,%3}, {%4,%5,%6,%7}, {%8,%9}, {%0,%1,%2,%3};"
        : "+f"(c[0]), "+f"(c[1]), "+f"(c[2]), "+f"(c[3])
        : "r"(a0), "r"(a1), "r"(a2), "r"(a3), "r"(b0), "r"(b1));
}

// ---------------- fused GEMM + gt-transpose + src/dst exp tables + den zero ----------------
__global__ __launch_bounds__(256) void gemm_fused(const float* __restrict__ A,
                                                  const float* __restrict__ W,
                                                  const float* __restrict__ av,
                                                  float* __restrict__ es,
                                                  float* __restrict__ es2,
                                                  float* __restrict__ ed,
                                                  float* __restrict__ ed2,
                                                  __nv_bfloat16* __restrict__ gthi,
                                                  __nv_bfloat16* __restrict__ gtlo,
                                                  float* __restrict__ den) {
    __shared__ float As[16][68];
    __shared__ float Bs[16][68];
    __shared__ uint32_t T[64][65];
    const int m0 = blockIdx.y * 64;
    const int o0 = blockIdx.x * 64;
    const int tid = threadIdx.x;
    const int tx = tid & 15;
    const int ty = tid >> 4;

    const int gtid = (blockIdx.y * 4 + blockIdx.x) * 256 + tid;
    if (gtid < BB * HH * NN) den[gtid] = 0.f;

    unsigned long long acc2[4][2];
    #pragma unroll
    for (int a = 0; a < 4; a++) { acc2[a][0] = 0ull; acc2[a][1] = 0ull; }
    for (int k0 = 0; k0 < 256; k0 += 16) {
        const int c = tid & 15;
        const int r = tid >> 4;
        #pragma unroll
        for (int rr = 0; rr < 64; rr += 16) {
            As[c][r + rr] = A[(m0 + r + rr) * 256 + k0 + c];
            Bs[c][r + rr] = W[(o0 + r + rr) * 256 + k0 + c];
        }
        __syncthreads();
        #pragma unroll
        for (int kk = 0; kk < 16; kk++) {
            F4U2 a4, b4;
            a4.f = *(const float4*)&As[kk][ty * 4];
            b4.f = *(const float4*)&Bs[kk][tx * 4];
            const unsigned long long ap0 = pack2(a4.f.x, a4.f.x);
            const unsigned long long ap1 = pack2(a4.f.y, a4.f.y);
            const unsigned long long ap2 = pack2(a4.f.z, a4.f.z);
            const unsigned long long ap3 = pack2(a4.f.w, a4.f.w);
            ffma2(acc2[0][0], ap0, b4.u.x); ffma2(acc2[0][1], ap0, b4.u.y);
            ffma2(acc2[1][0], ap1, b4.u.x); ffma2(acc2[1][1], ap1, b4.u.y);
            ffma2(acc2[2][0], ap2, b4.u.x); ffma2(acc2[2][1], ap2, b4.u.y);
            ffma2(acc2[3][0], ap3, b4.u.x); ffma2(acc2[3][1], ap3, b4.u.y);
        }
        __syncthreads();
    }

    const int b  = m0 >> 10;
    const int j0 = m0 & 1023;
    const int h0 = o0 >> 5;

    float aws[4], awd[4];
    #pragma unroll
    for (int c = 0; c < 4; ++c) {
        const int d = (tx * 4 + c) & 31;
        aws[c] = av[d];
        awd[c] = av[32 + d];
    }

    float vv[4][4];
    #pragma unroll
    for (int a = 0; a < 4; a++) {
        F4U2 o;
        o.u.x = acc2[a][0];
        o.u.y = acc2[a][1];
        vv[a][0] = o.f.x; vv[a][1] = o.f.y; vv[a][2] = o.f.z; vv[a][3] = o.f.w;
        #pragma unroll
        for (int c = 0; c < 4; ++c) {
            const __nv_bfloat16 hi = __float2bfloat16(vv[a][c]);
            const __nv_bfloat16 lo = __float2bfloat16(vv[a][c] - __bfloat162float(hi));
            T[tx * 4 + c][ty * 4 + a] = (uint32_t)__bfloat16_as_ushort(hi)
                                      | ((uint32_t)__bfloat16_as_ushort(lo) << 16);
        }
    }

    #pragma unroll
    for (int a = 0; a < 4; a++) {
        float s = vv[a][0] * aws[0] + vv[a][1] * aws[1]
                + vv[a][2] * aws[2] + vv[a][3] * aws[3];
        float d = vv[a][0] * awd[0] + vv[a][1] * awd[1]
                + vv[a][2] * awd[2] + vv[a][3] * awd[3];
        #pragma unroll
        for (int off = 4; off; off >>= 1) {
            s += __shfl_down_sync(0xFFFFFFFFu, s, off, 8);
            d += __shfl_down_sync(0xFFFFFFFFu, d, off, 8);
        }
        if ((tx & 7) == 0) {
            const int h = h0 + (tx >> 3);
            const int n = j0 + ty * 4 + a;
            const int idx = (b * HH + h) * NN + n;
            es [idx] = __expf(s);
            es2[idx] = __expf(0.2f * s);
            ed [idx] = __expf(d);
            ed2[idx] = __expf(0.2f * d);
        }
    }

    __syncthreads();
    {
        const int dl = tid >> 2;
        const int mq = (tid & 3) * 16;
        __align__(16) unsigned short his[16];
        __align__(16) unsigned short los[16];
        #pragma unroll
        for (int k = 0; k < 16; ++k) {
            const uint32_t v = T[dl][mq + k];
            his[k] = (unsigned short)(v & 0xFFFF);
            los[k] = (unsigned short)(v >> 16);
        }
        const int h = h0 + (dl >> 5);
        const int d = dl & 31;
        const size_t base = (size_t)((b * HH + h) * 32 + d) * NN + j0 + mq;
        *(uint4*)&gthi[base]     = ((uint4*)his)[0];
        *(uint4*)&gthi[base + 8] = ((uint4*)his)[1];
        *(uint4*)&gtlo[base]     = ((uint4*)los)[0];
        *(uint4*)&gtlo[base + 8] = ((uint4*)los)[1];
    }
}

// ---------------- adj -> row bitmask AND column bitmask (one kernel) ----------------
// grid 32 blocks, block (32 lanes, 32 warps). Block handles i-rows [bi*32, bi*32+32).
__global__ __launch_bounds__(1024) void adjprep_k(const int* __restrict__ adj,
                                                  unsigned* __restrict__ adjb,
                                                  unsigned* __restrict__ adjbT) {
    __shared__ unsigned tileW[32][33];   // [row-in-tile][j-word]
    const int lane = threadIdx.x;
    const int wy   = threadIdx.y;        // row-in-tile / j-word for pass 2
    const int i    = blockIdx.x * 32 + wy;
    #pragma unroll 4
    for (int w = 0; w < 32; ++w) {
        const int v = adj[i * 1024 + w * 32 + lane];
        const unsigned m = __ballot_sync(0xFFFFFFFFu, v != 0);
        if (lane == 0) {
            adjb[i * 32 + w] = m;
            tileW[wy][w] = m;
        }
    }
    __syncthreads();
    // transpose: warp wy owns j-word jw = wy; lane r supplies row r's word
    const unsigned wrd = tileW[lane][wy];
    #pragma unroll 4
    for (int c = 0; c < 32; ++c) {
        const unsigned m2 = __ballot_sync(0xFFFFFFFFu, (wrd >> c) & 1u);
        if (lane == c) adjbT[(wy * 32 + c) * 32 + blockIdx.x] = m2;
    }
}

// ---------------- den[bh][j] += sum_{i chunk} adj * max(es*ed, es2*ed2) ----------------
// float2 staging + fully unrolled inner loops.
__global__ __launch_bounds__(512) void denom_k(const unsigned* __restrict__ adjbT,
                                               const float* __restrict__ es,
                                               const float* __restrict__ es2,
                                               const float* __restrict__ ed,
                                               const float* __restrict__ ed2,
                                               float* __restrict__ den) {
    __shared__ float2 essv[64];
    const int b = blockIdx.z, h = blockIdx.y, bh = b * HH + h;
    const int ic = blockIdx.x * 64;
    const int tid = threadIdx.x;
    if (tid < 64) essv[tid] = make_float2(es[bh * NN + ic + tid],
                                          es2[bh * NN + ic + tid]);
    __syncthreads();
    const int j0 = tid, j1 = tid + 512;
    const float edj0 = ed[bh * NN + j0], ed2j0 = ed2[bh * NN + j0];
    const float edj1 = ed[bh * NN + j1], ed2j1 = ed2[bh * NN + j1];
    const int wbase = ic >> 5;
    float a0 = 0.f, a1 = 0.f;
    #pragma unroll
    for (int w = 0; w < 2; ++w) {
        const unsigned word0 = adjbT[(size_t)j0 * 32 + wbase + w];
        const unsigned word1 = adjbT[(size_t)j1 * 32 + wbase + w];
        #pragma unroll
        for (int k = 0; k < 32; ++k) {
            const float2 e = essv[w * 32 + k];
            const float v0 = fmaxf(e.x * edj0, e.y * ed2j0);
            const float v1 = fmaxf(e.x * edj1, e.y * ed2j1);
            if ((word0 >> k) & 1u) a0 += v0;
            if ((word1 >> k) & 1u) a1 += v1;
        }
    }
    atomicAdd(&den[bh * NN + j0], a0);
    atomicAdd(&den[bh * NN + j1], a1);
}

// ---------------- attention via mma.sync bf16 (hi/lo 3-term), j-split x2 ----------------
#define GROW 272

__device__ __forceinline__ float wv(float esr, float es2r, float2 e,
                                    unsigned bits, int c) {
    const float v = fmaxf(esr * e.x, es2r * e.y);
    return ((bits >> c) & 1u) ? v : 0.0f;
}

__global__ __launch_bounds__(256) void attn_k(const unsigned* __restrict__ adjb,
                                              const float* __restrict__ es,
                                              const float* __restrict__ es2,
                                              const float* __restrict__ ed,
                                              const float* __restrict__ ed2,
                                              const float* __restrict__ den,
                                              const __nv_bfloat16* __restrict__ gthi,
                                              const __nv_bfloat16* __restrict__ gtlo,
                                              float* __restrict__ part0,
                                              float* __restrict__ part1) {
    __shared__ __align__(16) char GsHi[32 * GROW];
    __shared__ __align__(16) char GsLo[32 * GROW];
    __shared__ float2 eds[NN / 2];
    __shared__ unsigned adjw[128][17];
    const int b = blockIdx.z;
    const int h = blockIdx.y & 7, jh = blockIdx.y >> 3;
    const int bh = b * HH + h;
    const int jbase = jh * (NN / 2);
    const int i0 = blockIdx.x * 128;
    const int tid = threadIdx.x, wid = tid >> 5, lane = tid & 31;
    const int g = lane >> 2, t = lane & 3;

    for (int j = tid; j < NN / 2; j += 256) {
        const float r = 1.0f / den[bh * NN + jbase + j];
        eds[j] = make_float2(ed[bh * NN + jbase + j] * r,
                             ed2[bh * NN + jbase + j] * r);
    }
    for (int k = tid; k < 128 * 16; k += 256)
        adjw[k >> 4][k & 15] = adjb[(size_t)(i0 + (k >> 4)) * 32 + jh * 16 + (k & 15)];

    const int r0 = i0 + wid * 16 + g;
    const float es_0  = es [bh * NN + r0];
    const float es_1  = es [bh * NN + r0 + 8];
    const float es2_0 = es2[bh * NN + r0];
    const float es2_1 = es2[bh * NN + r0 + 8];

    float acc[4][4] = {};
    const uint32_t gsHiA = smem_u32(GsHi), gsLoA = smem_u32(GsLo);
    const int d_l  = ((lane >> 4) & 1) * 8 + (lane & 7);
    const int jo_l = ((lane >> 3) & 1) * 8;
    const uint32_t lmoff = (uint32_t)(d_l * GROW + jo_l * 2);

    const __nv_bfloat16* ghb = gthi + (size_t)bh * 32 * NN + jbase;
    const __nv_bfloat16* glb = gtlo + (size_t)bh * 32 * NN + jbase;

    for (int ck = 0; ck < NN / 2; ck += 128) {
        __syncthreads();
        #pragma unroll
        for (int q = 0; q < 2; ++q) {
            const int idx = tid + q * 256;
            const int d = idx >> 4, c16 = idx & 15;
            const uint4 vh = *(const uint4*)(ghb + (size_t)d * NN + ck + c16 * 8);
            const uint4 vl = *(const uint4*)(glb + (size_t)d * NN + ck + c16 * 8);
            *(uint4*)(GsHi + d * GROW + c16 * 16) = vh;
            *(uint4*)(GsLo + d * GROW + c16 * 16) = vl;
        }
        __syncthreads();
        #pragma unroll
        for (int kk = 0; kk < 128; kk += 16) {
            const int jc = ck + kk;
            const unsigned bits0 = adjw[wid * 16 + g][jc >> 5] >> (jc & 31);
            const unsigned bits1 = adjw[wid * 16 + g + 8][jc >> 5] >> (jc & 31);
            const float2 e0 = eds[jc + 2 * t];
            const float2 e1 = eds[jc + 2 * t + 1];
            const float2 e2 = eds[jc + 2 * t + 8];
            const float2 e3 = eds[jc + 2 * t + 9];
            const float w00 = wv(es_0, es2_0, e0, bits0, 2 * t);
            const float w01 = wv(es_0, es2_0, e1, bits0, 2 * t + 1);
            const float w02 = wv(es_0, es2_0, e2, bits0, 2 * t + 8);
            const float w03 = wv(es_0, es2_0, e3, bits0, 2 * t + 9);
            const float w10 = wv(es_1, es2_1, e0, bits1, 2 * t);
            const float w11 = wv(es_1, es2_1, e1, bits1, 2 * t + 1);
            const float w12 = wv(es_1, es2_1, e2, bits1, 2 * t + 8);
            const float w13 = wv(es_1, es2_1, e3, bits1, 2 * t + 9);
            const uint32_t ahi0 = cvt2(w01, w00);
            const uint32_t ahi1 = cvt2(w11, w10);
            const uint32_t ahi2 = cvt2(w03, w02);
            const uint32_t ahi3 = cvt2(w13, w12);
            const uint32_t alo0 = cvt2(w01 - __uint_as_float(ahi0 & 0xFFFF0000u),
                                       w00 - __uint_as_float(ahi0 << 16));
            const uint32_t alo1 = cvt2(w11 - __uint_as_float(ahi1 & 0xFFFF0000u),
                                       w10 - __uint_as_float(ahi1 << 16));
            const uint32_t alo2 = cvt2(w03 - __uint_as_float(ahi2 & 0xFFFF0000u),
                                       w02 - __uint_as_float(ahi2 << 16));
            const uint32_t alo3 = cvt2(w13 - __uint_as_float(ahi3 & 0xFFFF0000u),
                                       w12 - __uint_as_float(ahi3 << 16));
            uint32_t bh01[4], bh23[4], bl01[4], bl23[4];
            ldm_x4(bh01[0], bh01[1], bh01[2], bh01[3], gsHiA + lmoff + kk * 2);
            ldm_x4(bh23[0], bh23[1], bh23[2], bh23[3], gsHiA + lmoff + kk * 2 + 16 * GROW);
            ldm_x4(bl01[0], bl01[1], bl01[2], bl01[3], gsLoA + lmoff + kk * 2);
            ldm_x4(bl23[0], bl23[1], bl23[2], bl23[3], gsLoA + lmoff + kk * 2 + 16 * GROW);
            mma16816(acc[0], ahi0, ahi1, ahi2, ahi3, bh01[0], bh01[1]);
            mma16816(acc[0], ahi0, ahi1, ahi2, ahi3, bl01[0], bl01[1]);
            mma16816(acc[0], alo0, alo1, alo2, alo3, bh01[0], bh01[1]);
            mma16816(acc[1], ahi0, ahi1, ahi2, ahi3, bh01[2], bh01[3]);
            mma16816(acc[1], ahi0, ahi1, ahi2, ahi3, bl01[2], bl01[3]);
            mma16816(acc[1], alo0, alo1, alo2, alo3, bh01[2], bh01[3]);
            mma16816(acc[2], ahi0, ahi1, ahi2, ahi3, bh23[0], bh23[1]);
            mma16816(acc[2], ahi0, ahi1, ahi2, ahi3, bl23[0], bl23[1]);
            mma16816(acc[2], alo0, alo1, alo2, alo3, bh23[0], bh23[1]);
            mma16816(acc[3], ahi0, ahi1, ahi2, ahi3, bh23[2], bh23[3]);
            mma16816(acc[3], ahi0, ahi1, ahi2, ahi3, bl23[2], bl23[3]);
            mma16816(acc[3], alo0, alo1, alo2, alo3, bh23[2], bh23[3]);
        }
    }
    float* po = (jh ? part1 : part0) + (size_t)(b * NN + r0) * FF + h * 32;
    #pragma unroll
    for (int nt = 0; nt < 4; ++nt) {
        *(float2*)(po + nt * 8 + 2 * t) = make_float2(acc[nt][0], acc[nt][1]);
        *(float2*)(po + (size_t)8 * FF + nt * 8 + 2 * t) = make_float2(acc[nt][2], acc[nt][3]);
    }
}

// ---------------- BatchNorm over batch (B=4) + ReLU (+residual); sums 2 partials ----------------
template <bool ADDRES>
__global__ __launch_bounds__(256) void bn_k(const float* __restrict__ y0,
                                            const float* __restrict__ y1,
                                            const float* __restrict__ gamma,
                                            const float* __restrict__ beta,
                                            const float* __restrict__ resid,
                                            float* __restrict__ out) {
    const int p = blockIdx.x * 256 + threadIdx.x;
    const float v0 = y0[p]          + y1[p];
    const float v1 = y0[NF + p]     + y1[NF + p];
    const float v2 = y0[2 * NF + p] + y1[2 * NF + p];
    const float v3 = y0[3 * NF + p] + y1[3 * NF + p];
    const float mu = 0.25f * (v0 + v1 + v2 + v3);
    const float d0 = v0 - mu, d1 = v1 - mu, d2 = v2 - mu, d3 = v3 - mu;
    const float var = 0.25f * (d0 * d0 + d1 * d1 + d2 * d2 + d3 * d3);
    const float rs = rsqrtf(var + 1e-5f);
    const float ga = gamma[p] * rs;
    const float be = beta[p];
    float o0 = fmaxf(fmaf(ga, d0, be), 0.f);
    float o1 = fmaxf(fmaf(ga, d1, be), 0.f);
    float o2 = fmaxf(fmaf(ga, d2, be), 0.f);
    float o3 = fmaxf(fmaf(ga, d3, be), 0.f);
    if (ADDRES) {
        o0 += resid[p];
        o1 += resid[NF + p];
        o2 += resid[2 * NF + p];
        o3 += resid[3 * NF + p];
    }
    out[p] = o0;
    out[NF + p] = o1;
    out[2 * NF + p] = o2;
    out[3 * NF + p] = o3;
}

// ---------------- launch (single stream, 9 kernels) ----------------
extern "C" void kernel_launch(void* const* d_in, const int* in_sizes, int n_in,
                              void* d_out, int out_size) {
    const float* x  = (const float*)d_in[0];
    const int*  adj = (const int*)  d_in[1];
    const float* W1 = (const float*)d_in[2];
    const float* a1 = (const float*)d_in[3];
    const float* g1 = (const float*)d_in[4];
    const float* b1 = (const float*)d_in[5];
    const float* W2 = (const float*)d_in[6];
    const float* a2 = (const float*)d_in[7];
    const float* g2 = (const float*)d_in[8];
    const float* b2 = (const float*)d_in[9];
    float* out = (float*)d_out;

    static float *pp0 = nullptr, *pp1, *py, *pex, *pden;
    static unsigned *padjb, *padjbT;
    static __nv_bfloat16 *pgthi, *pgtlo;
    if (!pp0) {
        cudaGetSymbolAddress((void**)&pp0,    p0_buf);
        cudaGetSymbolAddress((void**)&pp1,    p1_buf);
        cudaGetSymbolAddress((void**)&py,     y_buf);
        cudaGetSymbolAddress((void**)&pex,    ex_buf);
        cudaGetSymbolAddress((void**)&pden,   den_buf);
        cudaGetSymbolAddress((void**)&padjb,  adjb_buf);
        cudaGetSymbolAddress((void**)&padjbT, adjbT_buf);
        cudaGetSymbolAddress((void**)&pgthi,  gthi_buf);
        cudaGetSymbolAddress((void**)&pgtlo,  gtlo_buf);
    }
    const int EXN = BB * HH * NN;
    float* pes  = pex;
    float* pes2 = pex + EXN;
    float* ped  = pex + 2 * EXN;
    float* ped2 = pex + 3 * EXN;

    adjprep_k<<<32, dim3(32, 32)>>>(adj, padjb, padjbT);

    // ---- layer 1 ----
    gemm_fused<<<dim3(4, 64), 256>>>(x, W1, a1, pes, pes2, ped, ped2,
                                     pgthi, pgtlo, pden);
    denom_k<<<dim3(16, 8, 4), 512>>>(padjbT, pes, pes2, ped, ped2, pden);
    attn_k<<<dim3(8, 16, 4), 256>>>(padjb, pes, pes2, ped, ped2, pden,
                                    pgthi, pgtlo, pp0, pp1);
    bn_k<false><<<1024, 256>>>(pp0, pp1, g1, b1, nullptr, py);

    // ---- layer 2 ----
    gemm_fused<<<dim3(4, 64), 256>>>(py, W2, a2, pes, pes2, ped, ped2,
                                     pgthi, pgtlo, pden);
    denom_k<<<dim3(16, 8, 4), 512>>>(padjbT, pes, pes2, ped, ped2, pden);
    attn_k<<<dim3(8, 16, 4), 256>>>(padjb, pes, pes2, ped, ped2, pden,
                                    pgthi, pgtlo, pp0, pp1);
    bn_k<true><<<1024, 256>>>(pp0, pp1, g2, b2, x, out);
}

// round 14
// speedup vs baseline: 1.2467x; 1.0002x over previous
#include <cuda_runtime.h>
#include <cuda_bf16.h>
#include <cstdint>

#define BB 4
#define NN 1024
#define FF 256
#define HH 8
#define NF (NN*FF)

// ---------------- scratch (no allocations allowed) ----------------
__device__ float p0_buf [BB*NN*FF];
__device__ float p1_buf [BB*NN*FF];
__device__ float y_buf  [BB*NN*FF];
__device__ float ex_buf [4*BB*HH*NN];   // es, es2, ed, ed2  each [bh][n]
__device__ float den_buf[BB*HH*NN];
__device__ unsigned adjb_buf [NN*32];   // row bits:  adjb[i][jw]
__device__ unsigned adjbT_buf[NN*32];   // col bits:  adjbT[j][iw]
__device__ __nv_bfloat16 gthi_buf[BB*HH*32*NN];   // G^T hi  [bh][d][j]
__device__ __nv_bfloat16 gtlo_buf[BB*HH*32*NN];   // G^T lo

// ---------------- f32x2 helpers ----------------
__device__ __forceinline__ unsigned long long pack2(float a, float b) {
    unsigned long long r;
    asm("mov.b64 %0, {%1, %2};" : "=l"(r) : "f"(a), "f"(b));
    return r;
}
__device__ __forceinline__ void ffma2(unsigned long long& acc,
                                      unsigned long long a, unsigned long long b) {
    asm("fma.rn.f32x2 %0, %1, %2, %0;" : "+l"(acc) : "l"(a), "l"(b));
}
union F4U2 { float4 f; ulonglong2 u; };

// ---------------- mma helpers ----------------
__device__ __forceinline__ uint32_t smem_u32(const void* p) {
    uint32_t a;
    asm("{ .reg .u64 t; cvta.to.shared.u64 t, %1; cvt.u32.u64 %0, t; }" : "=r"(a) : "l"(p));
    return a;
}
__device__ __forceinline__ uint32_t cvt2(float hi, float lo) {
    uint32_t r;
    asm("cvt.rn.bf16x2.f32 %0, %1, %2;" : "=r"(r) : "f"(hi), "f"(lo));
    return r;
}
__device__ __forceinline__ void ldm_x4(uint32_t& r0, uint32_t& r1, uint32_t& r2,
                                       uint32_t& r3, uint32_t addr) {
    asm volatile("ldmatrix.sync.aligned.m8n8.x4.shared.b16 {%0,%1,%2,%3}, [%4];"
                 : "=r"(r0), "=r"(r1), "=r"(r2), "=r"(r3) : "r"(addr));
}
__device__ __forceinline__ void mma16816(float* c, uint32_t a0, uint32_t a1,
                                         uint32_t a2, uint32_t a3,
                                         uint32_t b0, uint32_t b1) {
    asm volatile(
        "mma.sync.aligned.m16n8k16.row.col.f32.bf16.bf16.f32 "
        "{%0,%1,%2,%3}, {%4,%5,%6,%7}, {%8,%9}, {%0,%1,%2,%3};"
        : "+f"(c[0]), "+f"(c[1]), "+f"(c[2]), "+f"(c[3])
        : "r"(a0), "r"(a1), "r"(a2), "r"(a3), "r"(b0), "r"(b1));
}

// ---------------- fused GEMM + gt-transpose + src/dst exp tables + den zero ----------------
__global__ __launch_bounds__(256) void gemm_fused(const float* __restrict__ A,
                                                  const float* __restrict__ W,
                                                  const float* __restrict__ av,
                                                  float* __restrict__ es,
                                                  float* __restrict__ es2,
                                                  float* __restrict__ ed,
                                                  float* __restrict__ ed2,
                                                  __nv_bfloat16* __restrict__ gthi,
                                                  __nv_bfloat16* __restrict__ gtlo,
                                                  float* __restrict__ den) {
    __shared__ float As[16][68];
    __shared__ float Bs[16][68];
    __shared__ uint32_t T[64][65];
    const int m0 = blockIdx.y * 64;
    const int o0 = blockIdx.x * 64;
    const int tid = threadIdx.x;
    const int tx = tid & 15;
    const int ty = tid >> 4;

    const int gtid = (blockIdx.y * 4 + blockIdx.x) * 256 + tid;
    if (gtid < BB * HH * NN) den[gtid] = 0.f;

    unsigned long long acc2[4][2];
    #pragma unroll
    for (int a = 0; a < 4; a++) { acc2[a][0] = 0ull; acc2[a][1] = 0ull; }
    for (int k0 = 0; k0 < 256; k0 += 16) {
        const int c = tid & 15;
        const int r = tid >> 4;
        #pragma unroll
        for (int rr = 0; rr < 64; rr += 16) {
            As[c][r + rr] = A[(m0 + r + rr) * 256 + k0 + c];
            Bs[c][r + rr] = W[(o0 + r + rr) * 256 + k0 + c];
        }
        __syncthreads();
        #pragma unroll
        for (int kk = 0; kk < 16; kk++) {
            F4U2 a4, b4;
            a4.f = *(const float4*)&As[kk][ty * 4];
            b4.f = *(const float4*)&Bs[kk][tx * 4];
            const unsigned long long ap0 = pack2(a4.f.x, a4.f.x);
            const unsigned long long ap1 = pack2(a4.f.y, a4.f.y);
            const unsigned long long ap2 = pack2(a4.f.z, a4.f.z);
            const unsigned long long ap3 = pack2(a4.f.w, a4.f.w);
            ffma2(acc2[0][0], ap0, b4.u.x); ffma2(acc2[0][1], ap0, b4.u.y);
            ffma2(acc2[1][0], ap1, b4.u.x); ffma2(acc2[1][1], ap1, b4.u.y);
            ffma2(acc2[2][0], ap2, b4.u.x); ffma2(acc2[2][1], ap2, b4.u.y);
            ffma2(acc2[3][0], ap3, b4.u.x); ffma2(acc2[3][1], ap3, b4.u.y);
        }
        __syncthreads();
    }

    const int b  = m0 >> 10;
    const int j0 = m0 & 1023;
    const int h0 = o0 >> 5;

    float aws[4], awd[4];
    #pragma unroll
    for (int c = 0; c < 4; ++c) {
        const int d = (tx * 4 + c) & 31;
        aws[c] = av[d];
        awd[c] = av[32 + d];
    }

    float vv[4][4];
    #pragma unroll
    for (int a = 0; a < 4; a++) {
        F4U2 o;
        o.u.x = acc2[a][0];
        o.u.y = acc2[a][1];
        vv[a][0] = o.f.x; vv[a][1] = o.f.y; vv[a][2] = o.f.z; vv[a][3] = o.f.w;
        #pragma unroll
        for (int c = 0; c < 4; ++c) {
            const __nv_bfloat16 hi = __float2bfloat16(vv[a][c]);
            const __nv_bfloat16 lo = __float2bfloat16(vv[a][c] - __bfloat162float(hi));
            T[tx * 4 + c][ty * 4 + a] = (uint32_t)__bfloat16_as_ushort(hi)
                                      | ((uint32_t)__bfloat16_as_ushort(lo) << 16);
        }
    }

    #pragma unroll
    for (int a = 0; a < 4; a++) {
        float s = vv[a][0] * aws[0] + vv[a][1] * aws[1]
                + vv[a][2] * aws[2] + vv[a][3] * aws[3];
        float d = vv[a][0] * awd[0] + vv[a][1] * awd[1]
                + vv[a][2] * awd[2] + vv[a][3] * awd[3];
        #pragma unroll
        for (int off = 4; off; off >>= 1) {
            s += __shfl_down_sync(0xFFFFFFFFu, s, off, 8);
            d += __shfl_down_sync(0xFFFFFFFFu, d, off, 8);
        }
        if ((tx & 7) == 0) {
            const int h = h0 + (tx >> 3);
            const int n = j0 + ty * 4 + a;
            const int idx = (b * HH + h) * NN + n;
            es [idx] = __expf(s);
            es2[idx] = __expf(0.2f * s);
            ed [idx] = __expf(d);
            ed2[idx] = __expf(0.2f * d);
        }
    }

    __syncthreads();
    {
        const int dl = tid >> 2;
        const int mq = (tid & 3) * 16;
        __align__(16) unsigned short his[16];
        __align__(16) unsigned short los[16];
        #pragma unroll
        for (int k = 0; k < 16; ++k) {
            const uint32_t v = T[dl][mq + k];
            his[k] = (unsigned short)(v & 0xFFFF);
            los[k] = (unsigned short)(v >> 16);
        }
        const int h = h0 + (dl >> 5);
        const int d = dl & 31;
        const size_t base = (size_t)((b * HH + h) * 32 + d) * NN + j0 + mq;
        *(uint4*)&gthi[base]     = ((uint4*)his)[0];
        *(uint4*)&gthi[base + 8] = ((uint4*)his)[1];
        *(uint4*)&gtlo[base]     = ((uint4*)los)[0];
        *(uint4*)&gtlo[base + 8] = ((uint4*)los)[1];
    }
}

// ---------------- adj -> row + column bitmasks (one kernel) ----------------
__global__ __launch_bounds__(1024) void adjprep_k(const int* __restrict__ adj,
                                                  unsigned* __restrict__ adjb,
                                                  unsigned* __restrict__ adjbT) {
    __shared__ unsigned tileW[32][33];
    const int lane = threadIdx.x;
    const int wy   = threadIdx.y;
    const int i    = blockIdx.x * 32 + wy;
    #pragma unroll 4
    for (int w = 0; w < 32; ++w) {
        const int v = adj[i * 1024 + w * 32 + lane];
        const unsigned m = __ballot_sync(0xFFFFFFFFu, v != 0);
        if (lane == 0) {
            adjb[i * 32 + w] = m;
            tileW[wy][w] = m;
        }
    }
    __syncthreads();
    const unsigned wrd = tileW[lane][wy];
    #pragma unroll 4
    for (int c = 0; c < 32; ++c) {
        const unsigned m2 = __ballot_sync(0xFFFFFFFFu, (wrd >> c) & 1u);
        if (lane == c) adjbT[(wy * 32 + c) * 32 + blockIdx.x] = m2;
    }
}

// ---------------- den[bh][j] += sum_{i chunk} adj * max(es*ed, es2*ed2) ----------------
__global__ __launch_bounds__(512) void denom_k(const unsigned* __restrict__ adjbT,
                                               const float* __restrict__ es,
                                               const float* __restrict__ es2,
                                               const float* __restrict__ ed,
                                               const float* __restrict__ ed2,
                                               float* __restrict__ den) {
    __shared__ float2 essv[64];
    const int b = blockIdx.z, h = blockIdx.y, bh = b * HH + h;
    const int ic = blockIdx.x * 64;
    const int tid = threadIdx.x;
    if (tid < 64) essv[tid] = make_float2(es[bh * NN + ic + tid],
                                          es2[bh * NN + ic + tid]);
    __syncthreads();
    const int j0 = tid, j1 = tid + 512;
    const float edj0 = ed[bh * NN + j0], ed2j0 = ed2[bh * NN + j0];
    const float edj1 = ed[bh * NN + j1], ed2j1 = ed2[bh * NN + j1];
    const int wbase = ic >> 5;
    float a0 = 0.f, a1 = 0.f;
    #pragma unroll
    for (int w = 0; w < 2; ++w) {
        const unsigned word0 = adjbT[(size_t)j0 * 32 + wbase + w];
        const unsigned word1 = adjbT[(size_t)j1 * 32 + wbase + w];
        #pragma unroll
        for (int k = 0; k < 32; ++k) {
            const float2 e = essv[w * 32 + k];
            const float v0 = fmaxf(e.x * edj0, e.y * ed2j0);
            const float v1 = fmaxf(e.x * edj1, e.y * ed2j1);
            if ((word0 >> k) & 1u) a0 += v0;
            if ((word1 >> k) & 1u) a1 += v1;
        }
    }
    atomicAdd(&den[bh * NN + j0], a0);
    atomicAdd(&den[bh * NN + j1], a1);
}

// ---------------- attention via mma.sync bf16 (hi/lo 3-term), j-split x2 ----------------
#define GROW 272

__device__ __forceinline__ float wv(float esr, float es2r, float2 e,
                                    unsigned bits, int c) {
    const float v = fmaxf(esr * e.x, es2r * e.y);
    return ((bits >> c) & 1u) ? v : 0.0f;
}

__global__ __launch_bounds__(256) void attn_k(const unsigned* __restrict__ adjb,
                                              const float* __restrict__ es,
                                              const float* __restrict__ es2,
                                              const float* __restrict__ ed,
                                              const float* __restrict__ ed2,
                                              const float* __restrict__ den,
                                              const __nv_bfloat16* __restrict__ gthi,
                                              const __nv_bfloat16* __restrict__ gtlo,
                                              float* __restrict__ part0,
                                              float* __restrict__ part1) {
    __shared__ __align__(16) char GsHi[32 * GROW];
    __shared__ __align__(16) char GsLo[32 * GROW];
    __shared__ float2 eds[NN / 2];
    __shared__ unsigned adjw[128][17];
    const int b = blockIdx.z;
    const int h = blockIdx.y & 7, jh = blockIdx.y >> 3;
    const int bh = b * HH + h;
    const int jbase = jh * (NN / 2);
    const int i0 = blockIdx.x * 128;
    const int tid = threadIdx.x, wid = tid >> 5, lane = tid & 31;
    const int g = lane >> 2, t = lane & 3;

    for (int j = tid; j < NN / 2; j += 256) {
        const float r = 1.0f / den[bh * NN + jbase + j];
        eds[j] = make_float2(ed[bh * NN + jbase + j] * r,
                             ed2[bh * NN + jbase + j] * r);
    }
    for (int k = tid; k < 128 * 16; k += 256)
        adjw[k >> 4][k & 15] = adjb[(size_t)(i0 + (k >> 4)) * 32 + jh * 16 + (k & 15)];

    const int r0 = i0 + wid * 16 + g;
    const float es_0  = es [bh * NN + r0];
    const float es_1  = es [bh * NN + r0 + 8];
    const float es2_0 = es2[bh * NN + r0];
    const float es2_1 = es2[bh * NN + r0 + 8];

    float acc[4][4] = {};
    const uint32_t gsHiA = smem_u32(GsHi), gsLoA = smem_u32(GsLo);
    const int d_l  = ((lane >> 4) & 1) * 8 + (lane & 7);
    const int jo_l = ((lane >> 3) & 1) * 8;
    const uint32_t lmoff = (uint32_t)(d_l * GROW + jo_l * 2);

    const __nv_bfloat16* ghb = gthi + (size_t)bh * 32 * NN + jbase;
    const __nv_bfloat16* glb = gtlo + (size_t)bh * 32 * NN + jbase;

    for (int ck = 0; ck < NN / 2; ck += 128) {
        __syncthreads();
        #pragma unroll
        for (int q = 0; q < 2; ++q) {
            const int idx = tid + q * 256;
            const int d = idx >> 4, c16 = idx & 15;
            const uint4 vh = *(const uint4*)(ghb + (size_t)d * NN + ck + c16 * 8);
            const uint4 vl = *(const uint4*)(glb + (size_t)d * NN + ck + c16 * 8);
            *(uint4*)(GsHi + d * GROW + c16 * 16) = vh;
            *(uint4*)(GsLo + d * GROW + c16 * 16) = vl;
        }
        __syncthreads();
        // hoist adj words for this 128-j chunk (kk>>5 is compile-time below)
        unsigned cw0[4], cw1[4];
        #pragma unroll
        for (int w = 0; w < 4; ++w) {
            cw0[w] = adjw[wid * 16 + g][(ck >> 5) + w];
            cw1[w] = adjw[wid * 16 + g + 8][(ck >> 5) + w];
        }
        #pragma unroll
        for (int kk = 0; kk < 128; kk += 16) {
            // ---- B fragments first: LDS latency hides under W-gen ALU ----
            uint32_t bh01[4], bh23[4], bl01[4], bl23[4];
            ldm_x4(bh01[0], bh01[1], bh01[2], bh01[3], gsHiA + lmoff + kk * 2);
            ldm_x4(bh23[0], bh23[1], bh23[2], bh23[3], gsHiA + lmoff + kk * 2 + 16 * GROW);
            ldm_x4(bl01[0], bl01[1], bl01[2], bl01[3], gsLoA + lmoff + kk * 2);
            ldm_x4(bl23[0], bl23[1], bl23[2], bl23[3], gsLoA + lmoff + kk * 2 + 16 * GROW);
            // ---- A fragments (W) in-register ----
            const unsigned bits0 = cw0[kk >> 5] >> (kk & 31);
            const unsigned bits1 = cw1[kk >> 5] >> (kk & 31);
            const int jc = ck + kk;
            const float2 e0 = eds[jc + 2 * t];
            const float2 e1 = eds[jc + 2 * t + 1];
            const float2 e2 = eds[jc + 2 * t + 8];
            const float2 e3 = eds[jc + 2 * t + 9];
            const float w00 = wv(es_0, es2_0, e0, bits0, 2 * t);
            const float w01 = wv(es_0, es2_0, e1, bits0, 2 * t + 1);
            const float w02 = wv(es_0, es2_0, e2, bits0, 2 * t + 8);
            const float w03 = wv(es_0, es2_0, e3, bits0, 2 * t + 9);
            const float w10 = wv(es_1, es2_1, e0, bits1, 2 * t);
            const float w11 = wv(es_1, es2_1, e1, bits1, 2 * t + 1);
            const float w12 = wv(es_1, es2_1, e2, bits1, 2 * t + 8);
            const float w13 = wv(es_1, es2_1, e3, bits1, 2 * t + 9);
            const uint32_t ahi0 = cvt2(w01, w00);
            const uint32_t ahi1 = cvt2(w11, w10);
            const uint32_t ahi2 = cvt2(w03, w02);
            const uint32_t ahi3 = cvt2(w13, w12);
            const uint32_t alo0 = cvt2(w01 - __uint_as_float(ahi0 & 0xFFFF0000u),
                                       w00 - __uint_as_float(ahi0 << 16));
            const uint32_t alo1 = cvt2(w11 - __uint_as_float(ahi1 & 0xFFFF0000u),
                                       w10 - __uint_as_float(ahi1 << 16));
            const uint32_t alo2 = cvt2(w03 - __uint_as_float(ahi2 & 0xFFFF0000u),
                                       w02 - __uint_as_float(ahi2 << 16));
            const uint32_t alo3 = cvt2(w13 - __uint_as_float(ahi3 & 0xFFFF0000u),
                                       w12 - __uint_as_float(ahi3 << 16));
            // ---- 12 MMAs, round-robin over accumulators (dep distance 4) ----
            mma16816(acc[0], ahi0, ahi1, ahi2, ahi3, bh01[0], bh01[1]);
            mma16816(acc[1], ahi0, ahi1, ahi2, ahi3, bh01[2], bh01[3]);
            mma16816(acc[2], ahi0, ahi1, ahi2, ahi3, bh23[0], bh23[1]);
            mma16816(acc[3], ahi0, ahi1, ahi2, ahi3, bh23[2], bh23[3]);
            mma16816(acc[0], ahi0, ahi1, ahi2, ahi3, bl01[0], bl01[1]);
            mma16816(acc[1], ahi0, ahi1, ahi2, ahi3, bl01[2], bl01[3]);
            mma16816(acc[2], ahi0, ahi1, ahi2, ahi3, bl23[0], bl23[1]);
            mma16816(acc[3], ahi0, ahi1, ahi2, ahi3, bl23[2], bl23[3]);
            mma16816(acc[0], alo0, alo1, alo2, alo3, bh01[0], bh01[1]);
            mma16816(acc[1], alo0, alo1, alo2, alo3, bh01[2], bh01[3]);
            mma16816(acc[2], alo0, alo1, alo2, alo3, bh23[0], bh23[1]);
            mma16816(acc[3], alo0, alo1, alo2, alo3, bh23[2], bh23[3]);
        }
    }
    float* po = (jh ? part1 : part0) + (size_t)(b * NN + r0) * FF + h * 32;
    #pragma unroll
    for (int nt = 0; nt < 4; ++nt) {
        *(float2*)(po + nt * 8 + 2 * t) = make_float2(acc[nt][0], acc[nt][1]);
        *(float2*)(po + (size_t)8 * FF + nt * 8 + 2 * t) = make_float2(acc[nt][2], acc[nt][3]);
    }
}

// ---------------- BatchNorm over batch (B=4) + ReLU (+residual); sums 2 partials ----------------
template <bool ADDRES>
__global__ __launch_bounds__(256) void bn_k(const float* __restrict__ y0,
                                            const float* __restrict__ y1,
                                            const float* __restrict__ gamma,
                                            const float* __restrict__ beta,
                                            const float* __restrict__ resid,
                                            float* __restrict__ out) {
    const int p = blockIdx.x * 256 + threadIdx.x;
    const float v0 = y0[p]          + y1[p];
    const float v1 = y0[NF + p]     + y1[NF + p];
    const float v2 = y0[2 * NF + p] + y1[2 * NF + p];
    const float v3 = y0[3 * NF + p] + y1[3 * NF + p];
    const float mu = 0.25f * (v0 + v1 + v2 + v3);
    const float d0 = v0 - mu, d1 = v1 - mu, d2 = v2 - mu, d3 = v3 - mu;
    const float var = 0.25f * (d0 * d0 + d1 * d1 + d2 * d2 + d3 * d3);
    const float rs = rsqrtf(var + 1e-5f);
    const float ga = gamma[p] * rs;
    const float be = beta[p];
    float o0 = fmaxf(fmaf(ga, d0, be), 0.f);
    float o1 = fmaxf(fmaf(ga, d1, be), 0.f);
    float o2 = fmaxf(fmaf(ga, d2, be), 0.f);
    float o3 = fmaxf(fmaf(ga, d3, be), 0.f);
    if (ADDRES) {
        o0 += resid[p];
        o1 += resid[NF + p];
        o2 += resid[2 * NF + p];
        o3 += resid[3 * NF + p];
    }
    out[p] = o0;
    out[NF + p] = o1;
    out[2 * NF + p] = o2;
    out[3 * NF + p] = o3;
}

// ---------------- launch (single stream, 9 kernels) ----------------
extern "C" void kernel_launch(void* const* d_in, const int* in_sizes, int n_in,
                              void* d_out, int out_size) {
    const float* x  = (const float*)d_in[0];
    const int*  adj = (const int*)  d_in[1];
    const float* W1 = (const float*)d_in[2];
    const float* a1 = (const float*)d_in[3];
    const float* g1 = (const float*)d_in[4];
    const float* b1 = (const float*)d_in[5];
    const float* W2 = (const float*)d_in[6];
    const float* a2 = (const float*)d_in[7];
    const float* g2 = (const float*)d_in[8];
    const float* b2 = (const float*)d_in[9];
    float* out = (float*)d_out;

    static float *pp0 = nullptr, *pp1, *py, *pex, *pden;
    static unsigned *padjb, *padjbT;
    static __nv_bfloat16 *pgthi, *pgtlo;
    if (!pp0) {
        cudaGetSymbolAddress((void**)&pp0,    p0_buf);
        cudaGetSymbolAddress((void**)&pp1,    p1_buf);
        cudaGetSymbolAddress((void**)&py,     y_buf);
        cudaGetSymbolAddress((void**)&pex,    ex_buf);
        cudaGetSymbolAddress((void**)&pden,   den_buf);
        cudaGetSymbolAddress((void**)&padjb,  adjb_buf);
        cudaGetSymbolAddress((void**)&padjbT, adjbT_buf);
        cudaGetSymbolAddress((void**)&pgthi,  gthi_buf);
        cudaGetSymbolAddress((void**)&pgtlo,  gtlo_buf);
    }
    const int EXN = BB * HH * NN;
    float* pes  = pex;
    float* pes2 = pex + EXN;
    float* ped  = pex + 2 * EXN;
    float* ped2 = pex + 3 * EXN;

    adjprep_k<<<32, dim3(32, 32)>>>(adj, padjb, padjbT);

    // ---- layer 1 ----
    gemm_fused<<<dim3(4, 64), 256>>>(x, W1, a1, pes, pes2, ped, ped2,
                                     pgthi, pgtlo, pden);
    denom_k<<<dim3(16, 8, 4), 512>>>(padjbT, pes, pes2, ped, ped2, pden);
    attn_k<<<dim3(8, 16, 4), 256>>>(padjb, pes, pes2, ped, ped2, pden,
                                    pgthi, pgtlo, pp0, pp1);
    bn_k<false><<<1024, 256>>>(pp0, pp1, g1, b1, nullptr, py);

    // ---- layer 2 ----
    gemm_fused<<<dim3(4, 64), 256>>>(py, W2, a2, pes, pes2, ped, ped2,
                                     pgthi, pgtlo, pden);
    denom_k<<<dim3(16, 8, 4), 512>>>(padjbT, pes, pes2, ped, ped2, pden);
    attn_k<<<dim3(8, 16, 4), 256>>>(padjb, pes, pes2, ped, ped2, pden,
                                    pgthi, pgtlo, pp0, pp1);
    bn_k<true><<<1024, 256>>>(pp0, pp1, g2, b2, x, out);
}